// round 11
// baseline (speedup 1.0000x reference)
#include <cuda_runtime.h>
#include <cuda_bf16.h>
#include <math.h>
#include <stdint.h>

#define BATCH  4
#define LEN    2048
#define DMODEL 1024
#define DIN    2048
#define DSTATE 16
#define DTRANK 64
#define DCONV  4
#define ML     (BATCH * LEN)          // 8192 rows
#define RH     (ML / 2)               // 4096 rows per half
#define DBCW   (DTRANK + 2 * DSTATE)  // 96

// ---------------- fp32 scratch ----------------
__device__ float g_xz[(size_t)ML * 2 * DIN];   // in-proj output (xc | z)
__device__ float g_xc[(size_t)ML * DIN];       // conv+silu output
__device__ float g_dbc[(size_t)ML * DBCW];     // dt | B | C
__device__ float g_delta[(size_t)ML * DIN];    // softplus(dt @ W_dt + b)
__device__ float g_y[(size_t)ML * DIN];        // scan output (fp32)

// ---------------- bf16 hi/lo scratch (x-proj / delta path) ----------------
__device__ __align__(16) __nv_bfloat16 g_xch[(size_t)ML * DIN];
__device__ __align__(16) __nv_bfloat16 g_xcl[(size_t)ML * DIN];
__device__ __align__(16) __nv_bfloat16 g_Wxh[(size_t)DBCW * DIN];
__device__ __align__(16) __nv_bfloat16 g_Wxl[(size_t)DBCW * DIN];
__device__ __align__(16) __nv_bfloat16 g_dth[(size_t)ML * DTRANK];
__device__ __align__(16) __nv_bfloat16 g_dtl[(size_t)ML * DTRANK];
__device__ __align__(16) __nv_bfloat16 g_Wdth[(size_t)DIN * DTRANK];
__device__ __align__(16) __nv_bfloat16 g_Wdtl[(size_t)DIN * DTRANK];

// ---------------- int8 hi/lo scratch (in-proj / out-proj path) -------------
__device__ __align__(16) int8_t g_xqh[(size_t)ML * DMODEL];
__device__ __align__(16) int8_t g_xql[(size_t)ML * DMODEL];
__device__ __align__(16) int8_t g_Winqh[(size_t)2 * DIN * DMODEL];
__device__ __align__(16) int8_t g_Winql[(size_t)2 * DIN * DMODEL];
__device__ __align__(16) int8_t g_yqh[(size_t)ML * DIN];
__device__ __align__(16) int8_t g_yql[(size_t)ML * DIN];
__device__ __align__(16) int8_t g_Woutqh[(size_t)DMODEL * DIN];
__device__ __align__(16) int8_t g_Woutql[(size_t)DMODEL * DIN];
__device__ float g_sx[ML];
__device__ float g_sWin[2 * DIN];
__device__ float g_sy[ML];
__device__ float g_sWout[DMODEL];

// ---------------- PTX helpers (base sm_103-legal only) ----------------
__device__ __forceinline__ uint32_t s2u(const void* p) {
    uint32_t a;
    asm("{ .reg .u64 t; cvta.to.shared.u64 t, %1; cvt.u32.u64 %0, t; }" : "=r"(a) : "l"(p));
    return a;
}
__device__ __forceinline__ void cpasync16(uint32_t dst, const void* src, int sz) {
    asm volatile("cp.async.cg.shared.global [%0], [%1], 16, %2;"
                 :: "r"(dst), "l"(src), "r"(sz) : "memory");
}
__device__ __forceinline__ void ldsm4(uint32_t* r, uint32_t addr) {
    asm volatile("ldmatrix.sync.aligned.m8n8.x4.shared.b16 {%0,%1,%2,%3}, [%4];"
                 : "=r"(r[0]), "=r"(r[1]), "=r"(r[2]), "=r"(r[3]) : "r"(addr));
}
__device__ __forceinline__ void mma16816(float* d, const uint32_t* a,
                                         uint32_t b0, uint32_t b1) {
    asm volatile(
        "mma.sync.aligned.m16n8k16.row.col.f32.bf16.bf16.f32 "
        "{%0,%1,%2,%3}, {%4,%5,%6,%7}, {%8,%9}, {%0,%1,%2,%3};"
        : "+f"(d[0]), "+f"(d[1]), "+f"(d[2]), "+f"(d[3])
        : "r"(a[0]), "r"(a[1]), "r"(a[2]), "r"(a[3]), "r"(b0), "r"(b1));
}
__device__ __forceinline__ void mma_i8(int* d, const uint32_t* a,
                                       uint32_t b0, uint32_t b1) {
    asm volatile(
        "mma.sync.aligned.m16n8k32.row.col.s32.s8.s8.s32 "
        "{%0,%1,%2,%3}, {%4,%5,%6,%7}, {%8,%9}, {%0,%1,%2,%3};"
        : "+r"(d[0]), "+r"(d[1]), "+r"(d[2]), "+r"(d[3])
        : "r"(a[0]), "r"(a[1]), "r"(a[2]), "r"(a[3]), "r"(b0), "r"(b1));
}
#define SWZ(o) ((o) ^ (((o) >> 3) & 0x70))

// ============================================================================
// int8 two-digit GEMM (IMMA m16n8k32): C[m,n] = sa[m]*sb[n]*sum_k A'[m,k]B'[n,k]
//   where A ~ sa*(Ah + Al/128). Segments: Ah*Bl, Al*Bh, (acc+64)>>7, Ah*Bh.
//   CTA tile 128x128, BK=128 int8 (128B rows, SW128), 2-stage cp.async.
//   M % 128 == 0, K % 128 == 0; B rows >= N zero-filled; stores guarded n<N.
// ============================================================================
__global__ __launch_bounds__(256) void gemm_i8(
    const int8_t* __restrict__ Ah, const int8_t* __restrict__ Al,
    const int8_t* __restrict__ Bh, const int8_t* __restrict__ Bl,
    float* __restrict__ C, int N, int K,
    const float* __restrict__ sa, const float* __restrict__ sb)
{
    extern __shared__ char dsm[];
    char* base = (char*)((((uintptr_t)dsm) + 1023) & ~(uintptr_t)1023);
    const uint32_t sA[2] = { s2u(base),         s2u(base) + 16384 };
    const uint32_t sB[2] = { s2u(base) + 32768, s2u(base) + 49152 };

    const int tid = threadIdx.x, lane = tid & 31, wid = tid >> 5;
    const int wm = (wid >> 2) * 64, wn = (wid & 3) * 32;
    const int m0 = blockIdx.y * 128, n0 = blockIdx.x * 128;
    const int kcs = K >> 7, T = 3 * kcs;

    int acc[4][4][4];
#pragma unroll
    for (int i = 0; i < 4; i++)
#pragma unroll
        for (int j = 0; j < 4; j++)
#pragma unroll
            for (int r = 0; r < 4; r++) acc[i][j][r] = 0;

    auto loadChunk = [&](int c, int buf) {
        const int seg = c / kcs, kc = c - seg * kcs, koff = kc * 128;
        const int8_t* Ap = (seg == 1) ? Al : Ah;   // seg0: Ah*Bl, seg1: Al*Bh, seg2: Ah*Bh
        const int8_t* Bp = (seg == 0) ? Bl : Bh;
#pragma unroll
        for (int q = 0; q < 4; q++) {                  // A: 128 x 128 int8
            int idx = tid + q * 256, r = idx >> 3, c8 = idx & 7;
            uint32_t o = (uint32_t)(r * 128 + c8 * 16);
            cpasync16(sA[buf] + SWZ(o), Ap + (size_t)(m0 + r) * K + koff + c8 * 16, 16);
        }
#pragma unroll
        for (int q = 0; q < 4; q++) {                  // B: 128 x 128 int8 (zfill rows >= N)
            int idx = tid + q * 256, r = idx >> 3, c8 = idx & 7;
            int nr = n0 + r;
            int ok = (nr < N) ? 16 : 0;
            uint32_t o = (uint32_t)(r * 128 + c8 * 16);
            cpasync16(sB[buf] + SWZ(o),
                      Bp + (size_t)((nr < N) ? nr : 0) * K + koff + c8 * 16, ok);
        }
        asm volatile("cp.async.commit_group;" ::: "memory");
    };

    loadChunk(0, 0);
    for (int c = 0; c < T; c++) {
        const int buf = c & 1;
        if (c + 1 < T) {
            loadChunk(c + 1, buf ^ 1);
            asm volatile("cp.async.wait_group 1;" ::: "memory");
        } else {
            asm volatile("cp.async.wait_group 0;" ::: "memory");
        }
        __syncthreads();

        const int rsel = lane & 15;
#pragma unroll
        for (int kb = 0; kb < 128; kb += 32) {          // byte offsets
            const int kkb = kb + (lane & 16);
            uint32_t af[4][4], bfr[2][4];
#pragma unroll
            for (int mi = 0; mi < 4; mi++) {
                uint32_t o = (uint32_t)((wm + mi * 16 + rsel) * 128 + kkb);
                ldsm4(af[mi], sA[buf] + SWZ(o));
            }
#pragma unroll
            for (int nb = 0; nb < 2; nb++) {
                uint32_t o = (uint32_t)((wn + nb * 16 + rsel) * 128 + kkb);
                ldsm4(bfr[nb], sB[buf] + SWZ(o));
            }
#pragma unroll
            for (int mi = 0; mi < 4; mi++)
#pragma unroll
                for (int nj = 0; nj < 4; nj++)
                    mma_i8(acc[mi][nj], af[mi],
                           bfr[nj >> 1][nj & 1], bfr[nj >> 1][(nj & 1) + 2]);
        }
        __syncthreads();

        if (c == 2 * kcs - 1) {                         // cross terms done: /128
#pragma unroll
            for (int mi = 0; mi < 4; mi++)
#pragma unroll
                for (int nj = 0; nj < 4; nj++)
#pragma unroll
                    for (int r = 0; r < 4; r++)
                        acc[mi][nj][r] = (acc[mi][nj][r] + 64) >> 7;
        }
    }

    // epilogue: scale by sa[m]*sb[n]
#pragma unroll
    for (int mi = 0; mi < 4; mi++)
#pragma unroll
        for (int h = 0; h < 2; h++) {
            int m = m0 + wm + mi * 16 + (lane >> 2) + h * 8;
            float sam = sa[m];
#pragma unroll
            for (int nj = 0; nj < 4; nj++) {
                int n = n0 + wn + nj * 8 + (lane & 3) * 2;
                if (n < N) {
                    float v0 = sam * sb[n]     * (float)acc[mi][nj][h * 2 + 0];
                    float v1 = sam * sb[n + 1] * (float)acc[mi][nj][h * 2 + 1];
                    *(float2*)(C + (size_t)m * N + n) = make_float2(v0, v1);
                }
            }
        }
}

// ============================================================================
// split-bf16 GEMM (kept for x-proj / delta): see R6. EPI: 1 = softplus+bias,
// 2 = plain + fused dt hi/lo split.
// ============================================================================
template <int EPI>
__global__ __launch_bounds__(256) void gemm_hl(
    const __nv_bfloat16* __restrict__ Ah, const __nv_bfloat16* __restrict__ Al,
    const __nv_bfloat16* __restrict__ Bh, const __nv_bfloat16* __restrict__ Bl,
    float* __restrict__ C, int N, int K, const float* __restrict__ bias,
    __nv_bfloat16* __restrict__ dth, __nv_bfloat16* __restrict__ dtl)
{
    extern __shared__ char dsm[];
    char* base = (char*)((((uintptr_t)dsm) + 1023) & ~(uintptr_t)1023);
    const uint32_t sA[2] = { s2u(base),         s2u(base) + 16384 };
    const uint32_t sB[2] = { s2u(base) + 32768, s2u(base) + 49152 };

    const int tid = threadIdx.x, lane = tid & 31, wid = tid >> 5;
    const int wm = (wid >> 2) * 64, wn = (wid & 3) * 32;
    const int m0 = blockIdx.y * 128, n0 = blockIdx.x * 128;
    const int kcs = K >> 6, T = 3 * kcs;

    float acc[4][4][4];
#pragma unroll
    for (int i = 0; i < 4; i++)
#pragma unroll
        for (int j = 0; j < 4; j++)
#pragma unroll
            for (int r = 0; r < 4; r++) acc[i][j][r] = 0.f;

    auto loadChunk = [&](int c, int buf) {
        const int seg = c / kcs, kc = c - seg * kcs, koff = kc * 64;
        const __nv_bfloat16* Ap = (seg == 1) ? Al : Ah;
        const __nv_bfloat16* Bp = (seg == 2) ? Bl : Bh;
#pragma unroll
        for (int q = 0; q < 4; q++) {
            int idx = tid + q * 256, r = idx >> 3, c8 = idx & 7;
            uint32_t o = (uint32_t)(r * 128 + c8 * 16);
            cpasync16(sA[buf] + SWZ(o), Ap + (size_t)(m0 + r) * K + koff + c8 * 8, 16);
        }
#pragma unroll
        for (int q = 0; q < 4; q++) {
            int idx = tid + q * 256, r = idx >> 3, c8 = idx & 7;
            int nr = n0 + r;
            int ok = (nr < N) ? 16 : 0;
            uint32_t o = (uint32_t)(r * 128 + c8 * 16);
            cpasync16(sB[buf] + SWZ(o),
                      Bp + (size_t)((nr < N) ? nr : 0) * K + koff + c8 * 8, ok);
        }
        asm volatile("cp.async.commit_group;" ::: "memory");
    };

    loadChunk(0, 0);
    for (int c = 0; c < T; c++) {
        const int buf = c & 1;
        if (c + 1 < T) {
            loadChunk(c + 1, buf ^ 1);
            asm volatile("cp.async.wait_group 1;" ::: "memory");
        } else {
            asm volatile("cp.async.wait_group 0;" ::: "memory");
        }
        __syncthreads();

        const int rsel = lane & 15;
#pragma unroll
        for (int kb = 0; kb < 64; kb += 16) {
            const int kk = kb + ((lane & 16) >> 1);
            uint32_t af[4][4], bfr[2][4];
#pragma unroll
            for (int mi = 0; mi < 4; mi++) {
                uint32_t o = (uint32_t)((wm + mi * 16 + rsel) * 128 + kk * 2);
                ldsm4(af[mi], sA[buf] + SWZ(o));
            }
#pragma unroll
            for (int nb = 0; nb < 2; nb++) {
                uint32_t o = (uint32_t)((wn + nb * 16 + rsel) * 128 + kk * 2);
                ldsm4(bfr[nb], sB[buf] + SWZ(o));
            }
#pragma unroll
            for (int mi = 0; mi < 4; mi++)
#pragma unroll
                for (int nj = 0; nj < 4; nj++)
                    mma16816(acc[mi][nj], af[mi],
                             bfr[nj >> 1][nj & 1], bfr[nj >> 1][(nj & 1) + 2]);
        }
        __syncthreads();
    }

#pragma unroll
    for (int mi = 0; mi < 4; mi++)
#pragma unroll
        for (int h = 0; h < 2; h++) {
            int m = m0 + wm + mi * 16 + (lane >> 2) + h * 8;
#pragma unroll
            for (int nj = 0; nj < 4; nj++) {
                int n = n0 + wn + nj * 8 + (lane & 3) * 2;
                if (n < N) {
                    float v0 = acc[mi][nj][h * 2 + 0];
                    float v1 = acc[mi][nj][h * 2 + 1];
                    if (EPI == 1) {
                        v0 += bias[n];
                        v1 += bias[n + 1];
                        v0 = fmaxf(v0, 0.f) + log1pf(expf(-fabsf(v0)));
                        v1 = fmaxf(v1, 0.f) + log1pf(expf(-fabsf(v1)));
                    }
                    *(float2*)(C + (size_t)m * N + n) = make_float2(v0, v1);
                    if (EPI == 2 && n < DTRANK) {
                        __nv_bfloat16 h0 = __float2bfloat16(v0);
                        __nv_bfloat16 h1 = __float2bfloat16(v1);
                        __nv_bfloat16 l0 = __float2bfloat16(v0 - __bfloat162float(h0));
                        __nv_bfloat16 l1 = __float2bfloat16(v1 - __bfloat162float(h1));
                        size_t o = (size_t)m * DTRANK + n;
                        *(__nv_bfloat162*)(dth + o) = __nv_bfloat162(h0, h1);
                        *(__nv_bfloat162*)(dtl + o) = __nv_bfloat162(l0, l1);
                    }
                }
            }
        }
}

// ---------------- per-row amax + two-digit int8 quantization ----------------
// grid.x = rows (one block per row), 256 threads, K % 4 == 0, K <= 2048.
__global__ __launch_bounds__(256) void quant_rows(
    const float* __restrict__ src, int8_t* __restrict__ qh,
    int8_t* __restrict__ ql, float* __restrict__ sc, int K)
{
    const int row = blockIdx.x, tid = threadIdx.x;
    const float4* s4 = (const float4*)(src + (size_t)row * K);
    const int n4 = K >> 2;

    float4 v[2];
    float amax = 0.f;
    int cnt = 0;
    for (int i = tid; i < n4; i += 256) {
        float4 a = s4[i];
        v[cnt++] = a;
        amax = fmaxf(amax, fmaxf(fmaxf(fabsf(a.x), fabsf(a.y)),
                                 fmaxf(fabsf(a.z), fabsf(a.w))));
    }
#pragma unroll
    for (int o = 16; o; o >>= 1)
        amax = fmaxf(amax, __shfl_xor_sync(0xFFFFFFFFu, amax, o));
    __shared__ float red[8];
    if ((tid & 31) == 0) red[tid >> 5] = amax;
    __syncthreads();
    float m = fmaxf(fmaxf(fmaxf(red[0], red[1]), fmaxf(red[2], red[3])),
                    fmaxf(fmaxf(red[4], red[5]), fmaxf(red[6], red[7])));
    float s = (m > 0.f) ? m * (1.f / 127.f) : 1.f;
    float inv = 1.f / s;

    cnt = 0;
    for (int i = tid; i < n4; i += 256) {
        float4 a = v[cnt++];
        int h0 = __float2int_rn(a.x * inv), h1 = __float2int_rn(a.y * inv);
        int h2 = __float2int_rn(a.z * inv), h3 = __float2int_rn(a.w * inv);
        int l0 = __float2int_rn((a.x * inv - h0) * 128.f);
        int l1 = __float2int_rn((a.y * inv - h1) * 128.f);
        int l2 = __float2int_rn((a.z * inv - h2) * 128.f);
        int l3 = __float2int_rn((a.w * inv - h3) * 128.f);
        ((char4*)qh)[(size_t)row * n4 + i] =
            make_char4((signed char)h0, (signed char)h1, (signed char)h2, (signed char)h3);
        ((char4*)ql)[(size_t)row * n4 + i] =
            make_char4((signed char)l0, (signed char)l1, (signed char)l2, (signed char)l3);
    }
    if (tid == 0) sc[row] = s;
}

// ---------------- fp32 -> (hi, lo) bf16 split, contiguous ----------------
__global__ __launch_bounds__(256) void split_hl(
    const float* __restrict__ src, __nv_bfloat16* __restrict__ h,
    __nv_bfloat16* __restrict__ l, int n4)
{
    int i = blockIdx.x * 256 + threadIdx.x;
    if (i >= n4) return;
    float4 v = ((const float4*)src)[i];
    __nv_bfloat16 h0 = __float2bfloat16(v.x), h1 = __float2bfloat16(v.y);
    __nv_bfloat16 h2 = __float2bfloat16(v.z), h3 = __float2bfloat16(v.w);
    __nv_bfloat16 l0 = __float2bfloat16(v.x - __bfloat162float(h0));
    __nv_bfloat16 l1 = __float2bfloat16(v.y - __bfloat162float(h1));
    __nv_bfloat16 l2 = __float2bfloat16(v.z - __bfloat162float(h2));
    __nv_bfloat16 l3 = __float2bfloat16(v.w - __bfloat162float(h3));
    ((__nv_bfloat162*)h)[i * 2 + 0] = __nv_bfloat162(h0, h1);
    ((__nv_bfloat162*)h)[i * 2 + 1] = __nv_bfloat162(h2, h3);
    ((__nv_bfloat162*)l)[i * 2 + 0] = __nv_bfloat162(l0, l1);
    ((__nv_bfloat162*)l)[i * 2 + 1] = __nv_bfloat162(l2, l3);
}

// ---------------- causal depthwise conv (k=4) + bias + SiLU + bf16 split ----
__global__ __launch_bounds__(256) void conv_silu_kernel(
    const float* __restrict__ w, const float* __restrict__ bias, int b0)
{
    int idx = blockIdx.x * blockDim.x + threadIdx.x;
    if (idx >= RH * DIN) return;
    int d = idx & (DIN - 1);
    int l = (idx >> 11) & (LEN - 1);
    int b = b0 + (idx >> 22);

    float acc = bias[d];
    const float* wd = w + d * DCONV;
#pragma unroll
    for (int j = 0; j < DCONV; j++) {
        int ll = l - (DCONV - 1) + j;
        if (ll >= 0)
            acc = fmaf(wd[j], g_xz[((size_t)(b * LEN + ll)) * (2 * DIN) + d], acc);
    }
    float s = acc / (1.f + __expf(-acc));
    size_t gidx = ((size_t)(b * LEN + l)) * DIN + d;
    g_xc[gidx] = s;
    __nv_bfloat16 hi = __float2bfloat16(s);
    g_xch[gidx] = hi;
    g_xcl[gidx] = __float2bfloat16(s - __bfloat162float(hi));
}

// ---------------- selective scan + D skip + SiLU(z) gate (fp32 out) --------
__global__ __launch_bounds__(256) void scan_kernel(
    const float* __restrict__ A_raw, const float* __restrict__ Dp, int b0)
{
    const int b = b0 + blockIdx.y;
    const int d = blockIdx.x * 64 + (threadIdx.x >> 2);
    const int q = threadIdx.x & 3;
    const int n0 = q * 4;

    float A2[4];
#pragma unroll
    for (int n = 0; n < 4; n++)
        A2[n] = -expf(A_raw[(size_t)(n0 + n) * DIN + d]) * 1.4426950408889634f;
    const float Dd = Dp[d];

    float h[4] = {0.f, 0.f, 0.f, 0.f};
    const float* dbcb = g_dbc + (size_t)b * LEN * DBCW + DTRANK;
    const size_t base = (size_t)b * LEN;

    size_t r0 = base * DIN + d;
    float dlt = g_delta[r0];
    float xv  = g_xc[r0];
    float zv  = g_xz[base * (2 * DIN) + DIN + d];

    for (int l = 0; l < LEN; l++) {
        float c_dlt = dlt, c_x = xv, c_z = zv;
        int ln = (l + 1 < LEN) ? l + 1 : l;
        size_t rn = (base + ln) * DIN + d;
        dlt = g_delta[rn];
        xv  = g_xc[rn];
        zv  = g_xz[(base + ln) * (2 * DIN) + DIN + d];

        const float* bc = dbcb + (size_t)l * DBCW;
        float dx = c_dlt * c_x;
        float yv = 0.f;
#pragma unroll
        for (int n = 0; n < 4; n++) {
            float Bn = bc[n0 + n];
            float Cn = bc[DSTATE + n0 + n];
            float dA = exp2f(c_dlt * A2[n]);
            h[n] = fmaf(dA, h[n], Bn * dx);
            yv = fmaf(Cn, h[n], yv);
        }
        yv += __shfl_xor_sync(0xFFFFFFFFu, yv, 1);
        yv += __shfl_xor_sync(0xFFFFFFFFu, yv, 2);
        if (q == 0) {
            float y = fmaf(Dd, c_x, yv);
            float gate = c_z / (1.f + __expf(-c_z));
            g_y[(base + l) * DIN + d] = y * gate;
        }
    }
}

// ---------------- launch: 2 batch-half chains on 2 streams -----------------
extern "C" void kernel_launch(void* const* d_in, const int* in_sizes, int n_in,
                              void* d_out, int out_size)
{
    const float* x      = (const float*)d_in[0];
    const float* W_in   = (const float*)d_in[1];
    const float* conv_w = (const float*)d_in[2];
    const float* conv_b = (const float*)d_in[3];
    const float* W_x    = (const float*)d_in[4];
    const float* W_dt   = (const float*)d_in[5];
    const float* b_dt   = (const float*)d_in[6];
    const float* A_raw  = (const float*)d_in[7];
    const float* Dp     = (const float*)d_in[8];
    const float* W_out  = (const float*)d_in[9];
    float* out = (float*)d_out;

    float *p_xz, *p_dbc, *p_delta, *p_y;
    float *p_sx, *p_sWin, *p_sy, *p_sWout;
    __nv_bfloat16 *p_xch, *p_xcl, *p_Wxh, *p_Wxl, *p_dth, *p_dtl, *p_Wdth, *p_Wdtl;
    int8_t *p_xqh, *p_xql, *p_Winqh, *p_Winql, *p_yqh, *p_yql, *p_Woutqh, *p_Woutql;
    cudaGetSymbolAddress((void**)&p_xz,     g_xz);
    cudaGetSymbolAddress((void**)&p_dbc,    g_dbc);
    cudaGetSymbolAddress((void**)&p_delta,  g_delta);
    cudaGetSymbolAddress((void**)&p_y,      g_y);
    cudaGetSymbolAddress((void**)&p_xch,    g_xch);
    cudaGetSymbolAddress((void**)&p_xcl,    g_xcl);
    cudaGetSymbolAddress((void**)&p_Wxh,    g_Wxh);
    cudaGetSymbolAddress((void**)&p_Wxl,    g_Wxl);
    cudaGetSymbolAddress((void**)&p_dth,    g_dth);
    cudaGetSymbolAddress((void**)&p_dtl,    g_dtl);
    cudaGetSymbolAddress((void**)&p_Wdth,   g_Wdth);
    cudaGetSymbolAddress((void**)&p_Wdtl,   g_Wdtl);
    cudaGetSymbolAddress((void**)&p_xqh,    g_xqh);
    cudaGetSymbolAddress((void**)&p_xql,    g_xql);
    cudaGetSymbolAddress((void**)&p_Winqh,  g_Winqh);
    cudaGetSymbolAddress((void**)&p_Winql,  g_Winql);
    cudaGetSymbolAddress((void**)&p_yqh,    g_yqh);
    cudaGetSymbolAddress((void**)&p_yql,    g_yql);
    cudaGetSymbolAddress((void**)&p_Woutqh, g_Woutqh);
    cudaGetSymbolAddress((void**)&p_Woutql, g_Woutql);
    cudaGetSymbolAddress((void**)&p_sx,     g_sx);
    cudaGetSymbolAddress((void**)&p_sWin,   g_sWin);
    cudaGetSymbolAddress((void**)&p_sy,     g_sy);
    cudaGetSymbolAddress((void**)&p_sWout,  g_sWout);

    const int GSMEM = 1024 + 4 * 16384;
    static bool s_init = false;
    static cudaStream_t st0, st1, stw;
    static cudaEvent_t evS, evWin, evWx, evWdt, evWout, evD0, evD1;
    if (!s_init) {
        cudaFuncSetAttribute(gemm_hl<1>, cudaFuncAttributeMaxDynamicSharedMemorySize, GSMEM);
        cudaFuncSetAttribute(gemm_hl<2>, cudaFuncAttributeMaxDynamicSharedMemorySize, GSMEM);
        cudaFuncSetAttribute(gemm_i8,    cudaFuncAttributeMaxDynamicSharedMemorySize, GSMEM);
        cudaStreamCreateWithFlags(&st0, cudaStreamNonBlocking);
        cudaStreamCreateWithFlags(&st1, cudaStreamNonBlocking);
        cudaStreamCreateWithFlags(&stw, cudaStreamNonBlocking);
        cudaEventCreateWithFlags(&evS,    cudaEventDisableTiming);
        cudaEventCreateWithFlags(&evWin,  cudaEventDisableTiming);
        cudaEventCreateWithFlags(&evWx,   cudaEventDisableTiming);
        cudaEventCreateWithFlags(&evWdt,  cudaEventDisableTiming);
        cudaEventCreateWithFlags(&evWout, cudaEventDisableTiming);
        cudaEventCreateWithFlags(&evD0,   cudaEventDisableTiming);
        cudaEventCreateWithFlags(&evD1,   cudaEventDisableTiming);
        s_init = true;
    }

    cudaEventRecord(evS, 0);
    cudaStreamWaitEvent(st0, evS, 0);
    cudaStreamWaitEvent(st1, evS, 0);
    cudaStreamWaitEvent(stw, evS, 0);

    // weight preprocessing on stw
    quant_rows<<<2 * DIN, 256, 0, stw>>>(W_in, p_Winqh, p_Winql, p_sWin, DMODEL);
    cudaEventRecord(evWin, stw);
    split_hl<<<(DBCW * DIN / 4 + 255) / 256, 256, 0, stw>>>(
        W_x, p_Wxh, p_Wxl, DBCW * DIN / 4);
    cudaEventRecord(evWx, stw);
    split_hl<<<(DIN * DTRANK / 4 + 255) / 256, 256, 0, stw>>>(
        W_dt, p_Wdth, p_Wdtl, DIN * DTRANK / 4);
    cudaEventRecord(evWdt, stw);
    quant_rows<<<DMODEL, 256, 0, stw>>>(W_out, p_Woutqh, p_Woutql, p_sWout, DIN);
    cudaEventRecord(evWout, stw);

    for (int h = 0; h < 2; h++) {
        cudaStream_t s = h ? st1 : st0;
        const size_t r0 = (size_t)h * RH;

        // quantize x half
        quant_rows<<<RH, 256, 0, s>>>(x + r0 * DMODEL,
                                      p_xqh + r0 * DMODEL, p_xql + r0 * DMODEL,
                                      p_sx + r0, DMODEL);
        // in-proj int8 GEMM: (4096 x 4096) K=1024
        cudaStreamWaitEvent(s, evWin, 0);
        gemm_i8<<<dim3(32, RH / 128), 256, GSMEM, s>>>(
            p_xqh + r0 * DMODEL, p_xql + r0 * DMODEL, p_Winqh, p_Winql,
            p_xz + r0 * 2 * DIN, 4096, DMODEL, p_sx + r0, p_sWin);
        // conv + SiLU + xc bf16 split
        conv_silu_kernel<<<(RH * DIN + 255) / 256, 256, 0, s>>>(conv_w, conv_b, 2 * h);
        // x-proj bf16 GEMM (4096 x 96) K=2048, fused dt split
        cudaStreamWaitEvent(s, evWx, 0);
        gemm_hl<2><<<dim3(1, RH / 128), 256, GSMEM, s>>>(
            p_xch + r0 * DIN, p_xcl + r0 * DIN, p_Wxh, p_Wxl,
            p_dbc + r0 * DBCW, DBCW, DIN, nullptr,
            p_dth + r0 * DTRANK, p_dtl + r0 * DTRANK);
        // delta bf16 GEMM (4096 x 2048) K=64, fused bias+softplus
        cudaStreamWaitEvent(s, evWdt, 0);
        gemm_hl<1><<<dim3(16, RH / 128), 256, GSMEM, s>>>(
            p_dth + r0 * DTRANK, p_dtl + r0 * DTRANK, p_Wdth, p_Wdtl,
            p_delta + r0 * DIN, DIN, DTRANK, b_dt, nullptr, nullptr);
        // selective scan (fp32 y)
        scan_kernel<<<dim3(DIN / 64, 2), 256, 0, s>>>(A_raw, Dp, 2 * h);
        // quantize y half
        quant_rows<<<RH, 256, 0, s>>>(p_y + r0 * DIN,
                                      p_yqh + r0 * DIN, p_yql + r0 * DIN,
                                      p_sy + r0, DIN);
        // out-proj int8 GEMM (4096 x 1024) K=2048
        cudaStreamWaitEvent(s, evWout, 0);
        gemm_i8<<<dim3(8, RH / 128), 256, GSMEM, s>>>(
            p_yqh + r0 * DIN, p_yql + r0 * DIN, p_Woutqh, p_Woutql,
            out + r0 * DMODEL, DMODEL, DIN, p_sy + r0, p_sWout);
        cudaEventRecord(h ? evD1 : evD0, s);
    }

    cudaStreamWaitEvent(0, evD0, 0);
    cudaStreamWaitEvent(0, evD1, 0);
}

// round 13
// speedup vs baseline: 1.1117x; 1.1117x over previous
#include <cuda_runtime.h>
#include <cuda_bf16.h>
#include <math.h>
#include <stdint.h>

#define BATCH  4
#define LEN    2048
#define DMODEL 1024
#define DIN    2048
#define DSTATE 16
#define DTRANK 64
#define DCONV  4
#define ML     (BATCH * LEN)          // 8192 rows
#define RH     (ML / 2)               // 4096 rows per half
#define DBCW   (DTRANK + 2 * DSTATE)  // 96

// ---------------- fp32 scratch ----------------
__device__ float g_xz[(size_t)ML * 2 * DIN];   // in-proj output (xc | z)
__device__ float g_dbc[(size_t)ML * DBCW];     // dt | B | C
__device__ float g_delta[(size_t)ML * DIN];    // softplus(dt @ W_dt + b)

// ---------------- bf16 hi/lo scratch ----------------
__device__ __align__(16) __nv_bfloat16 g_xh[(size_t)ML * DMODEL];
__device__ __align__(16) __nv_bfloat16 g_xl[(size_t)ML * DMODEL];
__device__ __align__(16) __nv_bfloat16 g_Winh[(size_t)2 * DIN * DMODEL];
__device__ __align__(16) __nv_bfloat16 g_Winl[(size_t)2 * DIN * DMODEL];
__device__ __align__(16) __nv_bfloat16 g_xch[(size_t)ML * DIN];
__device__ __align__(16) __nv_bfloat16 g_xcl[(size_t)ML * DIN];
__device__ __align__(16) __nv_bfloat16 g_Wxh[(size_t)DBCW * DIN];
__device__ __align__(16) __nv_bfloat16 g_Wxl[(size_t)DBCW * DIN];
__device__ __align__(16) __nv_bfloat16 g_dth[(size_t)ML * DTRANK];
__device__ __align__(16) __nv_bfloat16 g_dtl[(size_t)ML * DTRANK];
__device__ __align__(16) __nv_bfloat16 g_Wdth[(size_t)DIN * DTRANK];
__device__ __align__(16) __nv_bfloat16 g_Wdtl[(size_t)DIN * DTRANK];
__device__ __align__(16) __nv_bfloat16 g_yh[(size_t)ML * DIN];
__device__ __align__(16) __nv_bfloat16 g_yl[(size_t)ML * DIN];
__device__ __align__(16) __nv_bfloat16 g_Wouth[(size_t)DMODEL * DIN];
__device__ __align__(16) __nv_bfloat16 g_Woutl[(size_t)DMODEL * DIN];

// ---------------- PTX helpers (base sm_103-legal only) ----------------
__device__ __forceinline__ uint32_t s2u(const void* p) {
    uint32_t a;
    asm("{ .reg .u64 t; cvta.to.shared.u64 t, %1; cvt.u32.u64 %0, t; }" : "=r"(a) : "l"(p));
    return a;
}
__device__ __forceinline__ void cpasync16(uint32_t dst, const void* src, int sz) {
    asm volatile("cp.async.cg.shared.global [%0], [%1], 16, %2;"
                 :: "r"(dst), "l"(src), "r"(sz) : "memory");
}
__device__ __forceinline__ void ldsm4(uint32_t* r, uint32_t addr) {
    asm volatile("ldmatrix.sync.aligned.m8n8.x4.shared.b16 {%0,%1,%2,%3}, [%4];"
                 : "=r"(r[0]), "=r"(r[1]), "=r"(r[2]), "=r"(r[3]) : "r"(addr));
}
__device__ __forceinline__ void mma16816(float* d, const uint32_t* a,
                                         uint32_t b0, uint32_t b1) {
    asm volatile(
        "mma.sync.aligned.m16n8k16.row.col.f32.bf16.bf16.f32 "
        "{%0,%1,%2,%3}, {%4,%5,%6,%7}, {%8,%9}, {%0,%1,%2,%3};"
        : "+f"(d[0]), "+f"(d[1]), "+f"(d[2]), "+f"(d[3])
        : "r"(a[0]), "r"(a[1]), "r"(a[2]), "r"(a[3]), "r"(b0), "r"(b1));
}
#define SWZ(o) ((o) ^ (((o) >> 3) & 0x70))

// ============================================================================
// split-bf16 GEMM (mma.sync):  C[m,n] = sum_k A[m,k]*B[n,k]
//   3 K-segments: Ah*Bh + Al*Bh + Ah*Bl.  CTA tile 128x128, BK=64,
//   2-stage cp.async double buffer, SW128 swizzle, 8 warps at 64x32.
//   EPI: 0 = plain store
//        1 = softplus(acc + bias[n])
//        2 = plain store + (n < DTRANK) fused bf16 hi/lo split into dth/dtl
// ============================================================================
template <int EPI>
__global__ __launch_bounds__(256) void gemm_hl(
    const __nv_bfloat16* __restrict__ Ah, const __nv_bfloat16* __restrict__ Al,
    const __nv_bfloat16* __restrict__ Bh, const __nv_bfloat16* __restrict__ Bl,
    float* __restrict__ C, int N, int K, const float* __restrict__ bias,
    __nv_bfloat16* __restrict__ dth, __nv_bfloat16* __restrict__ dtl)
{
    extern __shared__ char dsm[];
    char* base = (char*)((((uintptr_t)dsm) + 1023) & ~(uintptr_t)1023);
    const uint32_t sA[2] = { s2u(base),         s2u(base) + 16384 };
    const uint32_t sB[2] = { s2u(base) + 32768, s2u(base) + 49152 };

    const int tid = threadIdx.x, lane = tid & 31, wid = tid >> 5;
    const int wm = (wid >> 2) * 64, wn = (wid & 3) * 32;
    const int m0 = blockIdx.y * 128, n0 = blockIdx.x * 128;
    const int kcs = K >> 6, T = 3 * kcs;

    float acc[4][4][4];
#pragma unroll
    for (int i = 0; i < 4; i++)
#pragma unroll
        for (int j = 0; j < 4; j++)
#pragma unroll
            for (int r = 0; r < 4; r++) acc[i][j][r] = 0.f;

    auto loadChunk = [&](int c, int buf) {
        const int seg = c / kcs, kc = c - seg * kcs, koff = kc * 64;
        const __nv_bfloat16* Ap = (seg == 1) ? Al : Ah;
        const __nv_bfloat16* Bp = (seg == 2) ? Bl : Bh;
#pragma unroll
        for (int q = 0; q < 4; q++) {                  // A: 128 x 64
            int idx = tid + q * 256, r = idx >> 3, c8 = idx & 7;
            uint32_t o = (uint32_t)(r * 128 + c8 * 16);
            cpasync16(sA[buf] + SWZ(o), Ap + (size_t)(m0 + r) * K + koff + c8 * 8, 16);
        }
#pragma unroll
        for (int q = 0; q < 4; q++) {                  // B: 128 x 64 (zfill rows >= N)
            int idx = tid + q * 256, r = idx >> 3, c8 = idx & 7;
            int nr = n0 + r;
            int ok = (nr < N) ? 16 : 0;
            uint32_t o = (uint32_t)(r * 128 + c8 * 16);
            cpasync16(sB[buf] + SWZ(o),
                      Bp + (size_t)((nr < N) ? nr : 0) * K + koff + c8 * 8, ok);
        }
        asm volatile("cp.async.commit_group;" ::: "memory");
    };

    loadChunk(0, 0);
    for (int c = 0; c < T; c++) {
        const int buf = c & 1;
        if (c + 1 < T) {
            loadChunk(c + 1, buf ^ 1);
            asm volatile("cp.async.wait_group 1;" ::: "memory");
        } else {
            asm volatile("cp.async.wait_group 0;" ::: "memory");
        }
        __syncthreads();

        const int rsel = lane & 15;
#pragma unroll
        for (int kb = 0; kb < 64; kb += 16) {
            const int kk = kb + ((lane & 16) >> 1);
            uint32_t af[4][4], bfr[2][4];
#pragma unroll
            for (int mi = 0; mi < 4; mi++) {
                uint32_t o = (uint32_t)((wm + mi * 16 + rsel) * 128 + kk * 2);
                ldsm4(af[mi], sA[buf] + SWZ(o));
            }
#pragma unroll
            for (int nb = 0; nb < 2; nb++) {
                uint32_t o = (uint32_t)((wn + nb * 16 + rsel) * 128 + kk * 2);
                ldsm4(bfr[nb], sB[buf] + SWZ(o));
            }
#pragma unroll
            for (int mi = 0; mi < 4; mi++)
#pragma unroll
                for (int nj = 0; nj < 4; nj++)
                    mma16816(acc[mi][nj], af[mi],
                             bfr[nj >> 1][nj & 1], bfr[nj >> 1][(nj & 1) + 2]);
        }
        __syncthreads();
    }

    // epilogue
#pragma unroll
    for (int mi = 0; mi < 4; mi++)
#pragma unroll
        for (int h = 0; h < 2; h++) {
            int m = m0 + wm + mi * 16 + (lane >> 2) + h * 8;
#pragma unroll
            for (int nj = 0; nj < 4; nj++) {
                int n = n0 + wn + nj * 8 + (lane & 3) * 2;
                if (n < N) {
                    float v0 = acc[mi][nj][h * 2 + 0];
                    float v1 = acc[mi][nj][h * 2 + 1];
                    if (EPI == 1) {
                        v0 += bias[n];
                        v1 += bias[n + 1];
                        v0 = fmaxf(v0, 0.f) + log1pf(expf(-fabsf(v0)));
                        v1 = fmaxf(v1, 0.f) + log1pf(expf(-fabsf(v1)));
                    }
                    *(float2*)(C + (size_t)m * N + n) = make_float2(v0, v1);
                    if (EPI == 2 && n < DTRANK) {      // fused dt hi/lo split
                        __nv_bfloat16 h0 = __float2bfloat16(v0);
                        __nv_bfloat16 h1 = __float2bfloat16(v1);
                        __nv_bfloat16 l0 = __float2bfloat16(v0 - __bfloat162float(h0));
                        __nv_bfloat16 l1 = __float2bfloat16(v1 - __bfloat162float(h1));
                        size_t o = (size_t)m * DTRANK + n;
                        *(__nv_bfloat162*)(dth + o) = __nv_bfloat162(h0, h1);
                        *(__nv_bfloat162*)(dtl + o) = __nv_bfloat162(l0, l1);
                    }
                }
            }
        }
}

// ---------------- fp32 -> (hi, lo) bf16 split, contiguous ----------------
__global__ __launch_bounds__(256) void split_hl(
    const float* __restrict__ src, __nv_bfloat16* __restrict__ h,
    __nv_bfloat16* __restrict__ l, int n4)
{
    int i = blockIdx.x * 256 + threadIdx.x;
    if (i >= n4) return;
    float4 v = ((const float4*)src)[i];
    __nv_bfloat16 h0 = __float2bfloat16(v.x), h1 = __float2bfloat16(v.y);
    __nv_bfloat16 h2 = __float2bfloat16(v.z), h3 = __float2bfloat16(v.w);
    __nv_bfloat16 l0 = __float2bfloat16(v.x - __bfloat162float(h0));
    __nv_bfloat16 l1 = __float2bfloat16(v.y - __bfloat162float(h1));
    __nv_bfloat16 l2 = __float2bfloat16(v.z - __bfloat162float(h2));
    __nv_bfloat16 l3 = __float2bfloat16(v.w - __bfloat162float(h3));
    ((__nv_bfloat162*)h)[i * 2 + 0] = __nv_bfloat162(h0, h1);
    ((__nv_bfloat162*)h)[i * 2 + 1] = __nv_bfloat162(h2, h3);
    ((__nv_bfloat162*)l)[i * 2 + 0] = __nv_bfloat162(l0, l1);
    ((__nv_bfloat162*)l)[i * 2 + 1] = __nv_bfloat162(l2, l3);
}

// ---------------- causal depthwise conv (k=4) + bias + SiLU + bf16 split ----
// Processes 2 batches starting at b0; writes ONLY bf16 hi/lo (no fp32 copy).
__global__ __launch_bounds__(256) void conv_silu_kernel(
    const float* __restrict__ w, const float* __restrict__ bias, int b0)
{
    int idx = blockIdx.x * blockDim.x + threadIdx.x;
    if (idx >= RH * DIN) return;
    int d = idx & (DIN - 1);
    int l = (idx >> 11) & (LEN - 1);
    int b = b0 + (idx >> 22);

    float acc = bias[d];
    const float* wd = w + d * DCONV;
#pragma unroll
    for (int j = 0; j < DCONV; j++) {
        int ll = l - (DCONV - 1) + j;
        if (ll >= 0)
            acc = fmaf(wd[j], g_xz[((size_t)(b * LEN + ll)) * (2 * DIN) + d], acc);
    }
    float s = acc / (1.f + __expf(-acc));
    size_t gidx = ((size_t)(b * LEN + l)) * DIN + d;
    __nv_bfloat16 hi = __float2bfloat16(s);
    g_xch[gidx] = hi;
    g_xcl[gidx] = __float2bfloat16(s - __bfloat162float(hi));
}

// ---------------- selective scan + D skip + SiLU(z) gate + bf16 split ------
// grid (DIN/64, 2), 256 threads: 64 channels x 4 state-quads; batches b0+blockIdx.y
// xc reconstructed from bf16 hi/lo (error ~2^-17, negligible).
__global__ __launch_bounds__(256) void scan_kernel(
    const float* __restrict__ A_raw, const float* __restrict__ Dp, int b0)
{
    const int b = b0 + blockIdx.y;
    const int d = blockIdx.x * 64 + (threadIdx.x >> 2);
    const int q = threadIdx.x & 3;
    const int n0 = q * 4;

    float A2[4];
#pragma unroll
    for (int n = 0; n < 4; n++)
        A2[n] = -expf(A_raw[(size_t)(n0 + n) * DIN + d]) * 1.4426950408889634f;
    const float Dd = Dp[d];

    float h[4] = {0.f, 0.f, 0.f, 0.f};
    const float* dbcb = g_dbc + (size_t)b * LEN * DBCW + DTRANK;
    const size_t base = (size_t)b * LEN;

    // prefetch l = 0
    size_t r0 = base * DIN + d;
    float dlt = g_delta[r0];
    float xv  = __bfloat162float(g_xch[r0]) + __bfloat162float(g_xcl[r0]);
    float zv  = g_xz[base * (2 * DIN) + DIN + d];

    for (int l = 0; l < LEN; l++) {
        float c_dlt = dlt, c_x = xv, c_z = zv;
        int ln = (l + 1 < LEN) ? l + 1 : l;            // prefetch next
        size_t rn = (base + ln) * DIN + d;
        dlt = g_delta[rn];
        xv  = __bfloat162float(g_xch[rn]) + __bfloat162float(g_xcl[rn]);
        zv  = g_xz[(base + ln) * (2 * DIN) + DIN + d];

        const float* bc = dbcb + (size_t)l * DBCW;
        float dx = c_dlt * c_x;
        float yv = 0.f;
#pragma unroll
        for (int n = 0; n < 4; n++) {
            float Bn = bc[n0 + n];
            float Cn = bc[DSTATE + n0 + n];
            float dA = exp2f(c_dlt * A2[n]);
            h[n] = fmaf(dA, h[n], Bn * dx);
            yv = fmaf(Cn, h[n], yv);
        }
        yv += __shfl_xor_sync(0xFFFFFFFFu, yv, 1);
        yv += __shfl_xor_sync(0xFFFFFFFFu, yv, 2);
        if (q == 0) {
            float y = fmaf(Dd, c_x, yv);
            float gate = c_z / (1.f + __expf(-c_z));
            float o = y * gate;
            size_t oi = (base + l) * DIN + d;
            __nv_bfloat16 hi = __float2bfloat16(o);
            g_yh[oi] = hi;
            g_yl[oi] = __float2bfloat16(o - __bfloat162float(hi));
        }
    }
}

// ---------------- launch: 2 batch-half chains on 2 streams -----------------
extern "C" void kernel_launch(void* const* d_in, const int* in_sizes, int n_in,
                              void* d_out, int out_size)
{
    const float* x      = (const float*)d_in[0];
    const float* W_in   = (const float*)d_in[1];
    const float* conv_w = (const float*)d_in[2];
    const float* conv_b = (const float*)d_in[3];
    const float* W_x    = (const float*)d_in[4];
    const float* W_dt   = (const float*)d_in[5];
    const float* b_dt   = (const float*)d_in[6];
    const float* A_raw  = (const float*)d_in[7];
    const float* Dp     = (const float*)d_in[8];
    const float* W_out  = (const float*)d_in[9];
    float* out = (float*)d_out;

    float *p_xz, *p_dbc, *p_delta;
    __nv_bfloat16 *p_xh, *p_xl, *p_Winh, *p_Winl, *p_xch, *p_xcl, *p_Wxh, *p_Wxl;
    __nv_bfloat16 *p_dth, *p_dtl, *p_Wdth, *p_Wdtl, *p_yh, *p_yl, *p_Wouth, *p_Woutl;
    cudaGetSymbolAddress((void**)&p_xz,    g_xz);
    cudaGetSymbolAddress((void**)&p_dbc,   g_dbc);
    cudaGetSymbolAddress((void**)&p_delta, g_delta);
    cudaGetSymbolAddress((void**)&p_xh,    g_xh);
    cudaGetSymbolAddress((void**)&p_xl,    g_xl);
    cudaGetSymbolAddress((void**)&p_Winh,  g_Winh);
    cudaGetSymbolAddress((void**)&p_Winl,  g_Winl);
    cudaGetSymbolAddress((void**)&p_xch,   g_xch);
    cudaGetSymbolAddress((void**)&p_xcl,   g_xcl);
    cudaGetSymbolAddress((void**)&p_Wxh,   g_Wxh);
    cudaGetSymbolAddress((void**)&p_Wxl,   g_Wxl);
    cudaGetSymbolAddress((void**)&p_dth,   g_dth);
    cudaGetSymbolAddress((void**)&p_dtl,   g_dtl);
    cudaGetSymbolAddress((void**)&p_Wdth,  g_Wdth);
    cudaGetSymbolAddress((void**)&p_Wdtl,  g_Wdtl);
    cudaGetSymbolAddress((void**)&p_yh,    g_yh);
    cudaGetSymbolAddress((void**)&p_yl,    g_yl);
    cudaGetSymbolAddress((void**)&p_Wouth, g_Wouth);
    cudaGetSymbolAddress((void**)&p_Woutl, g_Woutl);

    const int GSMEM = 1024 + 4 * 16384;   // align slack + 2 stages x (A16K+B16K)
    static bool s_init = false;
    static cudaStream_t st0, st1, stw;
    static cudaEvent_t evS, evWin, evWx, evWdt, evWout, evD0, evD1;
    if (!s_init) {
        cudaFuncSetAttribute(gemm_hl<0>, cudaFuncAttributeMaxDynamicSharedMemorySize, GSMEM);
        cudaFuncSetAttribute(gemm_hl<1>, cudaFuncAttributeMaxDynamicSharedMemorySize, GSMEM);
        cudaFuncSetAttribute(gemm_hl<2>, cudaFuncAttributeMaxDynamicSharedMemorySize, GSMEM);
        cudaStreamCreateWithFlags(&st0, cudaStreamNonBlocking);
        cudaStreamCreateWithFlags(&st1, cudaStreamNonBlocking);
        cudaStreamCreateWithFlags(&stw, cudaStreamNonBlocking);
        cudaEventCreateWithFlags(&evS,    cudaEventDisableTiming);
        cudaEventCreateWithFlags(&evWin,  cudaEventDisableTiming);
        cudaEventCreateWithFlags(&evWx,   cudaEventDisableTiming);
        cudaEventCreateWithFlags(&evWdt,  cudaEventDisableTiming);
        cudaEventCreateWithFlags(&evWout, cudaEventDisableTiming);
        cudaEventCreateWithFlags(&evD0,   cudaEventDisableTiming);
        cudaEventCreateWithFlags(&evD1,   cudaEventDisableTiming);
        s_init = true;
    }

    // fork from the origin (capture) stream
    cudaEventRecord(evS, 0);
    cudaStreamWaitEvent(st0, evS, 0);
    cudaStreamWaitEvent(st1, evS, 0);
    cudaStreamWaitEvent(stw, evS, 0);

    // weight splits on stw
    split_hl<<<(2 * DIN * DMODEL / 4 + 255) / 256, 256, 0, stw>>>(
        W_in, p_Winh, p_Winl, 2 * DIN * DMODEL / 4);
    cudaEventRecord(evWin, stw);
    split_hl<<<(DBCW * DIN / 4 + 255) / 256, 256, 0, stw>>>(
        W_x, p_Wxh, p_Wxl, DBCW * DIN / 4);
    cudaEventRecord(evWx, stw);
    split_hl<<<(DIN * DTRANK / 4 + 255) / 256, 256, 0, stw>>>(
        W_dt, p_Wdth, p_Wdtl, DIN * DTRANK / 4);
    cudaEventRecord(evWdt, stw);
    split_hl<<<(DMODEL * DIN / 4 + 255) / 256, 256, 0, stw>>>(
        W_out, p_Wouth, p_Woutl, DMODEL * DIN / 4);
    cudaEventRecord(evWout, stw);

    // two batch-half chains
    for (int h = 0; h < 2; h++) {
        cudaStream_t s = h ? st1 : st0;
        const size_t r0 = (size_t)h * RH;

        // split x half
        split_hl<<<(RH * DMODEL / 4 + 255) / 256, 256, 0, s>>>(
            x + r0 * DMODEL, p_xh + r0 * DMODEL, p_xl + r0 * DMODEL, RH * DMODEL / 4);
        // in-proj GEMM: (4096 x 4096) K=1024
        cudaStreamWaitEvent(s, evWin, 0);
        gemm_hl<0><<<dim3(32, RH / 128), 256, GSMEM, s>>>(
            p_xh + r0 * DMODEL, p_xl + r0 * DMODEL, p_Winh, p_Winl,
            p_xz + r0 * 2 * DIN, 4096, DMODEL, nullptr, nullptr, nullptr);
        // conv + SiLU + xc bf16 split (no fp32 copy)
        conv_silu_kernel<<<(RH * DIN + 255) / 256, 256, 0, s>>>(conv_w, conv_b, 2 * h);
        // x-proj GEMM (4096 x 96) K=2048, fused dt split
        cudaStreamWaitEvent(s, evWx, 0);
        gemm_hl<2><<<dim3(1, RH / 128), 256, GSMEM, s>>>(
            p_xch + r0 * DIN, p_xcl + r0 * DIN, p_Wxh, p_Wxl,
            p_dbc + r0 * DBCW, DBCW, DIN, nullptr,
            p_dth + r0 * DTRANK, p_dtl + r0 * DTRANK);
        // delta GEMM (4096 x 2048) K=64, fused bias+softplus
        cudaStreamWaitEvent(s, evWdt, 0);
        gemm_hl<1><<<dim3(16, RH / 128), 256, GSMEM, s>>>(
            p_dth + r0 * DTRANK, p_dtl + r0 * DTRANK, p_Wdth, p_Wdtl,
            p_delta + r0 * DIN, DIN, DTRANK, b_dt, nullptr, nullptr);
        // selective scan (2 batches)
        scan_kernel<<<dim3(DIN / 64, 2), 256, 0, s>>>(A_raw, Dp, 2 * h);
        // out-proj GEMM (4096 x 1024) K=2048
        cudaStreamWaitEvent(s, evWout, 0);
        gemm_hl<0><<<dim3(8, RH / 128), 256, GSMEM, s>>>(
            p_yh + r0 * DIN, p_yl + r0 * DIN, p_Wouth, p_Woutl,
            out + r0 * DMODEL, DMODEL, DIN, nullptr, nullptr, nullptr);
        cudaEventRecord(h ? evD1 : evD0, s);
    }

    // join back onto the origin stream
    cudaStreamWaitEvent(0, evD0, 0);
    cudaStreamWaitEvent(0, evD1, 0);
}

// round 14
// speedup vs baseline: 1.2060x; 1.0848x over previous
#include <cuda_runtime.h>
#include <cuda_bf16.h>
#include <math.h>
#include <stdint.h>

#define BATCH  4
#define LEN    2048
#define DMODEL 1024
#define DIN    2048
#define DSTATE 16
#define DTRANK 64
#define DCONV  4
#define ML     (BATCH * LEN)          // 8192 rows
#define RH     (ML / 2)               // 4096 rows per half
#define DBCW   (DTRANK + 2 * DSTATE)  // 96

// ---------------- fp32 scratch ----------------
__device__ float g_xz[(size_t)ML * 2 * DIN];   // in-proj output (xc | z)
__device__ float g_xc[(size_t)ML * DIN];       // conv+silu output (fp32 for scan)
__device__ float g_dbc[(size_t)ML * DBCW];     // dt | B | C
__device__ float g_delta[(size_t)ML * DIN];    // softplus(dt @ W_dt + b)

// ---------------- bf16 hi/lo scratch ----------------
__device__ __align__(16) __nv_bfloat16 g_xh[(size_t)ML * DMODEL];
__device__ __align__(16) __nv_bfloat16 g_xl[(size_t)ML * DMODEL];
__device__ __align__(16) __nv_bfloat16 g_Winh[(size_t)2 * DIN * DMODEL];
__device__ __align__(16) __nv_bfloat16 g_Winl[(size_t)2 * DIN * DMODEL];
__device__ __align__(16) __nv_bfloat16 g_xch[(size_t)ML * DIN];
__device__ __align__(16) __nv_bfloat16 g_xcl[(size_t)ML * DIN];
__device__ __align__(16) __nv_bfloat16 g_Wxh[(size_t)DBCW * DIN];
__device__ __align__(16) __nv_bfloat16 g_Wxl[(size_t)DBCW * DIN];
__device__ __align__(16) __nv_bfloat16 g_dth[(size_t)ML * DTRANK];
__device__ __align__(16) __nv_bfloat16 g_dtl[(size_t)ML * DTRANK];
__device__ __align__(16) __nv_bfloat16 g_Wdth[(size_t)DIN * DTRANK];
__device__ __align__(16) __nv_bfloat16 g_Wdtl[(size_t)DIN * DTRANK];
__device__ __align__(16) __nv_bfloat16 g_yh[(size_t)ML * DIN];
__device__ __align__(16) __nv_bfloat16 g_yl[(size_t)ML * DIN];
__device__ __align__(16) __nv_bfloat16 g_Wouth[(size_t)DMODEL * DIN];
__device__ __align__(16) __nv_bfloat16 g_Woutl[(size_t)DMODEL * DIN];

// ---------------- PTX helpers (base sm_103-legal only) ----------------
__device__ __forceinline__ uint32_t s2u(const void* p) {
    uint32_t a;
    asm("{ .reg .u64 t; cvta.to.shared.u64 t, %1; cvt.u32.u64 %0, t; }" : "=r"(a) : "l"(p));
    return a;
}
__device__ __forceinline__ void cpasync16(uint32_t dst, const void* src, int sz) {
    asm volatile("cp.async.cg.shared.global [%0], [%1], 16, %2;"
                 :: "r"(dst), "l"(src), "r"(sz) : "memory");
}
__device__ __forceinline__ void ldsm4(uint32_t* r, uint32_t addr) {
    asm volatile("ldmatrix.sync.aligned.m8n8.x4.shared.b16 {%0,%1,%2,%3}, [%4];"
                 : "=r"(r[0]), "=r"(r[1]), "=r"(r[2]), "=r"(r[3]) : "r"(addr));
}
__device__ __forceinline__ void mma16816(float* d, const uint32_t* a,
                                         uint32_t b0, uint32_t b1) {
    asm volatile(
        "mma.sync.aligned.m16n8k16.row.col.f32.bf16.bf16.f32 "
        "{%0,%1,%2,%3}, {%4,%5,%6,%7}, {%8,%9}, {%0,%1,%2,%3};"
        : "+f"(d[0]), "+f"(d[1]), "+f"(d[2]), "+f"(d[3])
        : "r"(a[0]), "r"(a[1]), "r"(a[2]), "r"(a[3]), "r"(b0), "r"(b1));
}
#define SWZ(o) ((o) ^ (((o) >> 3) & 0x70))

// ============================================================================
// split-bf16 GEMM (mma.sync):  C[m,n] = sum_k A[m,k]*B[n,k]
//   3 K-segments: Ah*Bh + Al*Bh + Ah*Bl.  CTA tile 128x128, BK=64,
//   2-stage cp.async double buffer, SW128 swizzle, 8 warps at 64x32.
//   EPI: 0 = plain store
//        1 = softplus(acc + bias[n])
//        2 = plain store + (n < DTRANK) fused bf16 hi/lo split into dth/dtl
// ============================================================================
template <int EPI>
__global__ __launch_bounds__(256) void gemm_hl(
    const __nv_bfloat16* __restrict__ Ah, const __nv_bfloat16* __restrict__ Al,
    const __nv_bfloat16* __restrict__ Bh, const __nv_bfloat16* __restrict__ Bl,
    float* __restrict__ C, int N, int K, const float* __restrict__ bias,
    __nv_bfloat16* __restrict__ dth, __nv_bfloat16* __restrict__ dtl)
{
    extern __shared__ char dsm[];
    char* base = (char*)((((uintptr_t)dsm) + 1023) & ~(uintptr_t)1023);
    const uint32_t sA[2] = { s2u(base),         s2u(base) + 16384 };
    const uint32_t sB[2] = { s2u(base) + 32768, s2u(base) + 49152 };

    const int tid = threadIdx.x, lane = tid & 31, wid = tid >> 5;
    const int wm = (wid >> 2) * 64, wn = (wid & 3) * 32;
    const int m0 = blockIdx.y * 128, n0 = blockIdx.x * 128;
    const int kcs = K >> 6, T = 3 * kcs;

    float acc[4][4][4];
#pragma unroll
    for (int i = 0; i < 4; i++)
#pragma unroll
        for (int j = 0; j < 4; j++)
#pragma unroll
            for (int r = 0; r < 4; r++) acc[i][j][r] = 0.f;

    auto loadChunk = [&](int c, int buf) {
        const int seg = c / kcs, kc = c - seg * kcs, koff = kc * 64;
        const __nv_bfloat16* Ap = (seg == 1) ? Al : Ah;
        const __nv_bfloat16* Bp = (seg == 2) ? Bl : Bh;
#pragma unroll
        for (int q = 0; q < 4; q++) {                  // A: 128 x 64
            int idx = tid + q * 256, r = idx >> 3, c8 = idx & 7;
            uint32_t o = (uint32_t)(r * 128 + c8 * 16);
            cpasync16(sA[buf] + SWZ(o), Ap + (size_t)(m0 + r) * K + koff + c8 * 8, 16);
        }
#pragma unroll
        for (int q = 0; q < 4; q++) {                  // B: 128 x 64 (zfill rows >= N)
            int idx = tid + q * 256, r = idx >> 3, c8 = idx & 7;
            int nr = n0 + r;
            int ok = (nr < N) ? 16 : 0;
            uint32_t o = (uint32_t)(r * 128 + c8 * 16);
            cpasync16(sB[buf] + SWZ(o),
                      Bp + (size_t)((nr < N) ? nr : 0) * K + koff + c8 * 8, ok);
        }
        asm volatile("cp.async.commit_group;" ::: "memory");
    };

    loadChunk(0, 0);
    for (int c = 0; c < T; c++) {
        const int buf = c & 1;
        if (c + 1 < T) {
            loadChunk(c + 1, buf ^ 1);
            asm volatile("cp.async.wait_group 1;" ::: "memory");
        } else {
            asm volatile("cp.async.wait_group 0;" ::: "memory");
        }
        __syncthreads();

        const int rsel = lane & 15;
#pragma unroll
        for (int kb = 0; kb < 64; kb += 16) {
            const int kk = kb + ((lane & 16) >> 1);
            uint32_t af[4][4], bfr[2][4];
#pragma unroll
            for (int mi = 0; mi < 4; mi++) {
                uint32_t o = (uint32_t)((wm + mi * 16 + rsel) * 128 + kk * 2);
                ldsm4(af[mi], sA[buf] + SWZ(o));
            }
#pragma unroll
            for (int nb = 0; nb < 2; nb++) {
                uint32_t o = (uint32_t)((wn + nb * 16 + rsel) * 128 + kk * 2);
                ldsm4(bfr[nb], sB[buf] + SWZ(o));
            }
#pragma unroll
            for (int mi = 0; mi < 4; mi++)
#pragma unroll
                for (int nj = 0; nj < 4; nj++)
                    mma16816(acc[mi][nj], af[mi],
                             bfr[nj >> 1][nj & 1], bfr[nj >> 1][(nj & 1) + 2]);
        }
        __syncthreads();
    }

    // epilogue
#pragma unroll
    for (int mi = 0; mi < 4; mi++)
#pragma unroll
        for (int h = 0; h < 2; h++) {
            int m = m0 + wm + mi * 16 + (lane >> 2) + h * 8;
#pragma unroll
            for (int nj = 0; nj < 4; nj++) {
                int n = n0 + wn + nj * 8 + (lane & 3) * 2;
                if (n < N) {
                    float v0 = acc[mi][nj][h * 2 + 0];
                    float v1 = acc[mi][nj][h * 2 + 1];
                    if (EPI == 1) {
                        v0 += bias[n];
                        v1 += bias[n + 1];
                        v0 = fmaxf(v0, 0.f) + log1pf(expf(-fabsf(v0)));
                        v1 = fmaxf(v1, 0.f) + log1pf(expf(-fabsf(v1)));
                    }
                    *(float2*)(C + (size_t)m * N + n) = make_float2(v0, v1);
                    if (EPI == 2 && n < DTRANK) {      // fused dt hi/lo split
                        __nv_bfloat16 h0 = __float2bfloat16(v0);
                        __nv_bfloat16 h1 = __float2bfloat16(v1);
                        __nv_bfloat16 l0 = __float2bfloat16(v0 - __bfloat162float(h0));
                        __nv_bfloat16 l1 = __float2bfloat16(v1 - __bfloat162float(h1));
                        size_t o = (size_t)m * DTRANK + n;
                        *(__nv_bfloat162*)(dth + o) = __nv_bfloat162(h0, h1);
                        *(__nv_bfloat162*)(dtl + o) = __nv_bfloat162(l0, l1);
                    }
                }
            }
        }
}

// ---------------- fp32 -> (hi, lo) bf16 split, contiguous ----------------
__global__ __launch_bounds__(256) void split_hl(
    const float* __restrict__ src, __nv_bfloat16* __restrict__ h,
    __nv_bfloat16* __restrict__ l, int n4)
{
    int i = blockIdx.x * 256 + threadIdx.x;
    if (i >= n4) return;
    float4 v = ((const float4*)src)[i];
    __nv_bfloat16 h0 = __float2bfloat16(v.x), h1 = __float2bfloat16(v.y);
    __nv_bfloat16 h2 = __float2bfloat16(v.z), h3 = __float2bfloat16(v.w);
    __nv_bfloat16 l0 = __float2bfloat16(v.x - __bfloat162float(h0));
    __nv_bfloat16 l1 = __float2bfloat16(v.y - __bfloat162float(h1));
    __nv_bfloat16 l2 = __float2bfloat16(v.z - __bfloat162float(h2));
    __nv_bfloat16 l3 = __float2bfloat16(v.w - __bfloat162float(h3));
    ((__nv_bfloat162*)h)[i * 2 + 0] = __nv_bfloat162(h0, h1);
    ((__nv_bfloat162*)h)[i * 2 + 1] = __nv_bfloat162(h2, h3);
    ((__nv_bfloat162*)l)[i * 2 + 0] = __nv_bfloat162(l0, l1);
    ((__nv_bfloat162*)l)[i * 2 + 1] = __nv_bfloat162(l2, l3);
}

// ---------------- causal depthwise conv (k=4) + bias + SiLU + bf16 split ----
// Processes 2 batches starting at b0; grid covers RH*DIN elements.
__global__ __launch_bounds__(256) void conv_silu_kernel(
    const float* __restrict__ w, const float* __restrict__ bias, int b0)
{
    int idx = blockIdx.x * blockDim.x + threadIdx.x;
    if (idx >= RH * DIN) return;
    int d = idx & (DIN - 1);
    int l = (idx >> 11) & (LEN - 1);
    int b = b0 + (idx >> 22);

    float acc = bias[d];
    const float* wd = w + d * DCONV;
#pragma unroll
    for (int j = 0; j < DCONV; j++) {
        int ll = l - (DCONV - 1) + j;
        if (ll >= 0)
            acc = fmaf(wd[j], g_xz[((size_t)(b * LEN + ll)) * (2 * DIN) + d], acc);
    }
    float s = acc / (1.f + __expf(-acc));
    size_t gidx = ((size_t)(b * LEN + l)) * DIN + d;
    g_xc[gidx] = s;
    __nv_bfloat16 hi = __float2bfloat16(s);
    g_xch[gidx] = hi;
    g_xcl[gidx] = __float2bfloat16(s - __bfloat162float(hi));
}

// ---------------- selective scan + D skip + SiLU(z) gate + bf16 split ------
// grid (DIN/64, 2), 256 threads: 64 channels x 4 state-quads; batches b0+blockIdx.y
__global__ __launch_bounds__(256) void scan_kernel(
    const float* __restrict__ A_raw, const float* __restrict__ Dp, int b0)
{
    const int b = b0 + blockIdx.y;
    const int d = blockIdx.x * 64 + (threadIdx.x >> 2);
    const int q = threadIdx.x & 3;
    const int n0 = q * 4;

    float A2[4];
#pragma unroll
    for (int n = 0; n < 4; n++)
        A2[n] = -expf(A_raw[(size_t)(n0 + n) * DIN + d]) * 1.4426950408889634f;
    const float Dd = Dp[d];

    float h[4] = {0.f, 0.f, 0.f, 0.f};
    const float* dbcb = g_dbc + (size_t)b * LEN * DBCW + DTRANK;
    const size_t base = (size_t)b * LEN;

    // prefetch l = 0
    size_t r0 = base * DIN + d;
    float dlt = g_delta[r0];
    float xv  = g_xc[r0];
    float zv  = g_xz[base * (2 * DIN) + DIN + d];

    for (int l = 0; l < LEN; l++) {
        float c_dlt = dlt, c_x = xv, c_z = zv;
        int ln = (l + 1 < LEN) ? l + 1 : l;            // prefetch next
        size_t rn = (base + ln) * DIN + d;
        dlt = g_delta[rn];
        xv  = g_xc[rn];
        zv  = g_xz[(base + ln) * (2 * DIN) + DIN + d];

        const float* bc = dbcb + (size_t)l * DBCW;
        float dx = c_dlt * c_x;
        float yv = 0.f;
#pragma unroll
        for (int n = 0; n < 4; n++) {
            float Bn = bc[n0 + n];
            float Cn = bc[DSTATE + n0 + n];
            float dA = exp2f(c_dlt * A2[n]);
            h[n] = fmaf(dA, h[n], Bn * dx);
            yv = fmaf(Cn, h[n], yv);
        }
        yv += __shfl_xor_sync(0xFFFFFFFFu, yv, 1);
        yv += __shfl_xor_sync(0xFFFFFFFFu, yv, 2);
        if (q == 0) {
            float y = fmaf(Dd, c_x, yv);
            float gate = c_z / (1.f + __expf(-c_z));
            float o = y * gate;
            size_t oi = (base + l) * DIN + d;
            __nv_bfloat16 hi = __float2bfloat16(o);
            g_yh[oi] = hi;
            g_yl[oi] = __float2bfloat16(o - __bfloat162float(hi));
        }
    }
}

// ---------------- launch: 2 STAGGERED batch-half chains on 2 streams --------
extern "C" void kernel_launch(void* const* d_in, const int* in_sizes, int n_in,
                              void* d_out, int out_size)
{
    const float* x      = (const float*)d_in[0];
    const float* W_in   = (const float*)d_in[1];
    const float* conv_w = (const float*)d_in[2];
    const float* conv_b = (const float*)d_in[3];
    const float* W_x    = (const float*)d_in[4];
    const float* W_dt   = (const float*)d_in[5];
    const float* b_dt   = (const float*)d_in[6];
    const float* A_raw  = (const float*)d_in[7];
    const float* Dp     = (const float*)d_in[8];
    const float* W_out  = (const float*)d_in[9];
    float* out = (float*)d_out;

    float *p_xz, *p_dbc, *p_delta;
    __nv_bfloat16 *p_xh, *p_xl, *p_Winh, *p_Winl, *p_xch, *p_xcl, *p_Wxh, *p_Wxl;
    __nv_bfloat16 *p_dth, *p_dtl, *p_Wdth, *p_Wdtl, *p_yh, *p_yl, *p_Wouth, *p_Woutl;
    cudaGetSymbolAddress((void**)&p_xz,    g_xz);
    cudaGetSymbolAddress((void**)&p_dbc,   g_dbc);
    cudaGetSymbolAddress((void**)&p_delta, g_delta);
    cudaGetSymbolAddress((void**)&p_xh,    g_xh);
    cudaGetSymbolAddress((void**)&p_xl,    g_xl);
    cudaGetSymbolAddress((void**)&p_Winh,  g_Winh);
    cudaGetSymbolAddress((void**)&p_Winl,  g_Winl);
    cudaGetSymbolAddress((void**)&p_xch,   g_xch);
    cudaGetSymbolAddress((void**)&p_xcl,   g_xcl);
    cudaGetSymbolAddress((void**)&p_Wxh,   g_Wxh);
    cudaGetSymbolAddress((void**)&p_Wxl,   g_Wxl);
    cudaGetSymbolAddress((void**)&p_dth,   g_dth);
    cudaGetSymbolAddress((void**)&p_dtl,   g_dtl);
    cudaGetSymbolAddress((void**)&p_Wdth,  g_Wdth);
    cudaGetSymbolAddress((void**)&p_Wdtl,  g_Wdtl);
    cudaGetSymbolAddress((void**)&p_yh,    g_yh);
    cudaGetSymbolAddress((void**)&p_yl,    g_yl);
    cudaGetSymbolAddress((void**)&p_Wouth, g_Wouth);
    cudaGetSymbolAddress((void**)&p_Woutl, g_Woutl);

    const int GSMEM = 1024 + 4 * 16384;   // align slack + 2 stages x (A16K+B16K)
    static bool s_init = false;
    static cudaStream_t st0, st1, stw;
    static cudaEvent_t evS, evWin, evWx, evWdt, evWout, evD0, evD1, evIP;
    if (!s_init) {
        cudaFuncSetAttribute(gemm_hl<0>, cudaFuncAttributeMaxDynamicSharedMemorySize, GSMEM);
        cudaFuncSetAttribute(gemm_hl<1>, cudaFuncAttributeMaxDynamicSharedMemorySize, GSMEM);
        cudaFuncSetAttribute(gemm_hl<2>, cudaFuncAttributeMaxDynamicSharedMemorySize, GSMEM);
        cudaStreamCreateWithFlags(&st0, cudaStreamNonBlocking);
        cudaStreamCreateWithFlags(&st1, cudaStreamNonBlocking);
        cudaStreamCreateWithFlags(&stw, cudaStreamNonBlocking);
        cudaEventCreateWithFlags(&evS,    cudaEventDisableTiming);
        cudaEventCreateWithFlags(&evWin,  cudaEventDisableTiming);
        cudaEventCreateWithFlags(&evWx,   cudaEventDisableTiming);
        cudaEventCreateWithFlags(&evWdt,  cudaEventDisableTiming);
        cudaEventCreateWithFlags(&evWout, cudaEventDisableTiming);
        cudaEventCreateWithFlags(&evD0,   cudaEventDisableTiming);
        cudaEventCreateWithFlags(&evD1,   cudaEventDisableTiming);
        cudaEventCreateWithFlags(&evIP,   cudaEventDisableTiming);
        s_init = true;
    }

    // fork from the origin (capture) stream
    cudaEventRecord(evS, 0);
    cudaStreamWaitEvent(st0, evS, 0);
    cudaStreamWaitEvent(st1, evS, 0);
    cudaStreamWaitEvent(stw, evS, 0);

    // weight splits on stw
    split_hl<<<(2 * DIN * DMODEL / 4 + 255) / 256, 256, 0, stw>>>(
        W_in, p_Winh, p_Winl, 2 * DIN * DMODEL / 4);
    cudaEventRecord(evWin, stw);
    split_hl<<<(DBCW * DIN / 4 + 255) / 256, 256, 0, stw>>>(
        W_x, p_Wxh, p_Wxl, DBCW * DIN / 4);
    cudaEventRecord(evWx, stw);
    split_hl<<<(DIN * DTRANK / 4 + 255) / 256, 256, 0, stw>>>(
        W_dt, p_Wdth, p_Wdtl, DIN * DTRANK / 4);
    cudaEventRecord(evWdt, stw);
    split_hl<<<(DMODEL * DIN / 4 + 255) / 256, 256, 0, stw>>>(
        W_out, p_Wouth, p_Woutl, DMODEL * DIN / 4);
    cudaEventRecord(evWout, stw);

    // two batch-half chains, STAGGERED: chain1's in-proj waits on chain0's
    for (int h = 0; h < 2; h++) {
        cudaStream_t s = h ? st1 : st0;
        const size_t r0 = (size_t)h * RH;

        // split x half
        split_hl<<<(RH * DMODEL / 4 + 255) / 256, 256, 0, s>>>(
            x + r0 * DMODEL, p_xh + r0 * DMODEL, p_xl + r0 * DMODEL, RH * DMODEL / 4);
        // in-proj GEMM: (4096 x 4096) K=1024
        cudaStreamWaitEvent(s, evWin, 0);
        if (h == 1) cudaStreamWaitEvent(s, evIP, 0);   // stagger: wait chain0 in-proj
        gemm_hl<0><<<dim3(32, RH / 128), 256, GSMEM, s>>>(
            p_xh + r0 * DMODEL, p_xl + r0 * DMODEL, p_Winh, p_Winl,
            p_xz + r0 * 2 * DIN, 4096, DMODEL, nullptr, nullptr, nullptr);
        if (h == 0) cudaEventRecord(evIP, s);          // chain0 in-proj done
        // conv + SiLU + xc bf16 split
        conv_silu_kernel<<<(RH * DIN + 255) / 256, 256, 0, s>>>(conv_w, conv_b, 2 * h);
        // x-proj GEMM (4096 x 96) K=2048, fused dt split
        cudaStreamWaitEvent(s, evWx, 0);
        gemm_hl<2><<<dim3(1, RH / 128), 256, GSMEM, s>>>(
            p_xch + r0 * DIN, p_xcl + r0 * DIN, p_Wxh, p_Wxl,
            p_dbc + r0 * DBCW, DBCW, DIN, nullptr,
            p_dth + r0 * DTRANK, p_dtl + r0 * DTRANK);
        // delta GEMM (4096 x 2048) K=64, fused bias+softplus
        cudaStreamWaitEvent(s, evWdt, 0);
        gemm_hl<1><<<dim3(16, RH / 128), 256, GSMEM, s>>>(
            p_dth + r0 * DTRANK, p_dtl + r0 * DTRANK, p_Wdth, p_Wdtl,
            p_delta + r0 * DIN, DIN, DTRANK, b_dt, nullptr, nullptr);
        // selective scan (2 batches)
        scan_kernel<<<dim3(DIN / 64, 2), 256, 0, s>>>(A_raw, Dp, 2 * h);
        // out-proj GEMM (4096 x 1024) K=2048
        cudaStreamWaitEvent(s, evWout, 0);
        gemm_hl<0><<<dim3(8, RH / 128), 256, GSMEM, s>>>(
            p_yh + r0 * DIN, p_yl + r0 * DIN, p_Wouth, p_Woutl,
            out + r0 * DMODEL, DMODEL, DIN, nullptr, nullptr, nullptr);
        cudaEventRecord(h ? evD1 : evD0, s);
    }

    // join back onto the origin stream
    cudaStreamWaitEvent(0, evD0, 0);
    cudaStreamWaitEvent(0, evD1, 0);
}

// round 15
// speedup vs baseline: 1.5232x; 1.2630x over previous
#include <cuda_runtime.h>
#include <cuda_bf16.h>
#include <math.h>
#include <stdint.h>

#define BATCH  4
#define LEN    2048
#define DMODEL 1024
#define DIN    2048
#define DSTATE 16
#define DTRANK 64
#define DCONV  4
#define ML     (BATCH * LEN)          // 8192 rows
#define RH     (ML / 2)               // 4096 rows per half
#define DBCW   (DTRANK + 2 * DSTATE)  // 96

// ---------------- fp32 scratch ----------------
__device__ float g_xz[(size_t)ML * 2 * DIN];   // in-proj output (xc | z)
__device__ float g_xc[(size_t)ML * DIN];       // conv+silu output (fp32 for scan)
__device__ float g_dbc[(size_t)ML * DBCW];     // dt | B | C
__device__ float g_delta[(size_t)ML * DIN];    // softplus(dt @ W_dt + b)

// ---------------- bf16 hi/lo scratch ----------------
__device__ __align__(16) __nv_bfloat16 g_xh[(size_t)ML * DMODEL];
__device__ __align__(16) __nv_bfloat16 g_xl[(size_t)ML * DMODEL];
__device__ __align__(16) __nv_bfloat16 g_Winh[(size_t)2 * DIN * DMODEL];
__device__ __align__(16) __nv_bfloat16 g_Winl[(size_t)2 * DIN * DMODEL];
__device__ __align__(16) __nv_bfloat16 g_xch[(size_t)ML * DIN];
__device__ __align__(16) __nv_bfloat16 g_xcl[(size_t)ML * DIN];
__device__ __align__(16) __nv_bfloat16 g_Wxh[(size_t)DBCW * DIN];
__device__ __align__(16) __nv_bfloat16 g_Wxl[(size_t)DBCW * DIN];
__device__ __align__(16) __nv_bfloat16 g_dth[(size_t)ML * DTRANK];
__device__ __align__(16) __nv_bfloat16 g_dtl[(size_t)ML * DTRANK];
__device__ __align__(16) __nv_bfloat16 g_Wdth[(size_t)DIN * DTRANK];
__device__ __align__(16) __nv_bfloat16 g_Wdtl[(size_t)DIN * DTRANK];
__device__ __align__(16) __nv_bfloat16 g_yh[(size_t)ML * DIN];
__device__ __align__(16) __nv_bfloat16 g_yl[(size_t)ML * DIN];
__device__ __align__(16) __nv_bfloat16 g_Wouth[(size_t)DMODEL * DIN];
__device__ __align__(16) __nv_bfloat16 g_Woutl[(size_t)DMODEL * DIN];

// ---------------- PTX helpers (base sm_103-legal only) ----------------
__device__ __forceinline__ uint32_t s2u(const void* p) {
    uint32_t a;
    asm("{ .reg .u64 t; cvta.to.shared.u64 t, %1; cvt.u32.u64 %0, t; }" : "=r"(a) : "l"(p));
    return a;
}
__device__ __forceinline__ void cpasync16(uint32_t dst, const void* src, int sz) {
    asm volatile("cp.async.cg.shared.global [%0], [%1], 16, %2;"
                 :: "r"(dst), "l"(src), "r"(sz) : "memory");
}
__device__ __forceinline__ void ldsm4(uint32_t* r, uint32_t addr) {
    asm volatile("ldmatrix.sync.aligned.m8n8.x4.shared.b16 {%0,%1,%2,%3}, [%4];"
                 : "=r"(r[0]), "=r"(r[1]), "=r"(r[2]), "=r"(r[3]) : "r"(addr));
}
__device__ __forceinline__ void mma16816(float* d, const uint32_t* a,
                                         uint32_t b0, uint32_t b1) {
    asm volatile(
        "mma.sync.aligned.m16n8k16.row.col.f32.bf16.bf16.f32 "
        "{%0,%1,%2,%3}, {%4,%5,%6,%7}, {%8,%9}, {%0,%1,%2,%3};"
        : "+f"(d[0]), "+f"(d[1]), "+f"(d[2]), "+f"(d[3])
        : "r"(a[0]), "r"(a[1]), "r"(a[2]), "r"(a[3]), "r"(b0), "r"(b1));
}
#define SWZ(o) ((o) ^ (((o) >> 3) & 0x70))

// ============================================================================
// split-bf16 GEMM (mma.sync):  C[m,n] = sum_k A[m,k]*B[n,k]
//   3 K-segments: Ah*Bh + Al*Bh + Ah*Bl.  CTA tile 128x128, BK=64,
//   2-stage cp.async double buffer, SW128 swizzle, 8 warps at 64x32.
//   EPI: 0 = plain store
//        1 = softplus(acc + bias[n])
//        2 = plain store + (n < DTRANK) fused bf16 hi/lo split into dth/dtl
// ============================================================================
template <int EPI>
__global__ __launch_bounds__(256) void gemm_hl(
    const __nv_bfloat16* __restrict__ Ah, const __nv_bfloat16* __restrict__ Al,
    const __nv_bfloat16* __restrict__ Bh, const __nv_bfloat16* __restrict__ Bl,
    float* __restrict__ C, int N, int K, const float* __restrict__ bias,
    __nv_bfloat16* __restrict__ dth, __nv_bfloat16* __restrict__ dtl)
{
    extern __shared__ char dsm[];
    char* base = (char*)((((uintptr_t)dsm) + 1023) & ~(uintptr_t)1023);
    const uint32_t sA[2] = { s2u(base),         s2u(base) + 16384 };
    const uint32_t sB[2] = { s2u(base) + 32768, s2u(base) + 49152 };

    const int tid = threadIdx.x, lane = tid & 31, wid = tid >> 5;
    const int wm = (wid >> 2) * 64, wn = (wid & 3) * 32;
    const int m0 = blockIdx.y * 128, n0 = blockIdx.x * 128;
    const int kcs = K >> 6, T = 3 * kcs;

    float acc[4][4][4];
#pragma unroll
    for (int i = 0; i < 4; i++)
#pragma unroll
        for (int j = 0; j < 4; j++)
#pragma unroll
            for (int r = 0; r < 4; r++) acc[i][j][r] = 0.f;

    auto loadChunk = [&](int c, int buf) {
        const int seg = c / kcs, kc = c - seg * kcs, koff = kc * 64;
        const __nv_bfloat16* Ap = (seg == 1) ? Al : Ah;
        const __nv_bfloat16* Bp = (seg == 2) ? Bl : Bh;
#pragma unroll
        for (int q = 0; q < 4; q++) {                  // A: 128 x 64
            int idx = tid + q * 256, r = idx >> 3, c8 = idx & 7;
            uint32_t o = (uint32_t)(r * 128 + c8 * 16);
            cpasync16(sA[buf] + SWZ(o), Ap + (size_t)(m0 + r) * K + koff + c8 * 8, 16);
        }
#pragma unroll
        for (int q = 0; q < 4; q++) {                  // B: 128 x 64 (zfill rows >= N)
            int idx = tid + q * 256, r = idx >> 3, c8 = idx & 7;
            int nr = n0 + r;
            int ok = (nr < N) ? 16 : 0;
            uint32_t o = (uint32_t)(r * 128 + c8 * 16);
            cpasync16(sB[buf] + SWZ(o),
                      Bp + (size_t)((nr < N) ? nr : 0) * K + koff + c8 * 8, ok);
        }
        asm volatile("cp.async.commit_group;" ::: "memory");
    };

    loadChunk(0, 0);
    for (int c = 0; c < T; c++) {
        const int buf = c & 1;
        if (c + 1 < T) {
            loadChunk(c + 1, buf ^ 1);
            asm volatile("cp.async.wait_group 1;" ::: "memory");
        } else {
            asm volatile("cp.async.wait_group 0;" ::: "memory");
        }
        __syncthreads();

        const int rsel = lane & 15;
#pragma unroll
        for (int kb = 0; kb < 64; kb += 16) {
            const int kk = kb + ((lane & 16) >> 1);
            uint32_t af[4][4], bfr[2][4];
#pragma unroll
            for (int mi = 0; mi < 4; mi++) {
                uint32_t o = (uint32_t)((wm + mi * 16 + rsel) * 128 + kk * 2);
                ldsm4(af[mi], sA[buf] + SWZ(o));
            }
#pragma unroll
            for (int nb = 0; nb < 2; nb++) {
                uint32_t o = (uint32_t)((wn + nb * 16 + rsel) * 128 + kk * 2);
                ldsm4(bfr[nb], sB[buf] + SWZ(o));
            }
#pragma unroll
            for (int mi = 0; mi < 4; mi++)
#pragma unroll
                for (int nj = 0; nj < 4; nj++)
                    mma16816(acc[mi][nj], af[mi],
                             bfr[nj >> 1][nj & 1], bfr[nj >> 1][(nj & 1) + 2]);
        }
        __syncthreads();
    }

    // epilogue
#pragma unroll
    for (int mi = 0; mi < 4; mi++)
#pragma unroll
        for (int h = 0; h < 2; h++) {
            int m = m0 + wm + mi * 16 + (lane >> 2) + h * 8;
#pragma unroll
            for (int nj = 0; nj < 4; nj++) {
                int n = n0 + wn + nj * 8 + (lane & 3) * 2;
                if (n < N) {
                    float v0 = acc[mi][nj][h * 2 + 0];
                    float v1 = acc[mi][nj][h * 2 + 1];
                    if (EPI == 1) {
                        v0 += bias[n];
                        v1 += bias[n + 1];
                        v0 = fmaxf(v0, 0.f) + log1pf(expf(-fabsf(v0)));
                        v1 = fmaxf(v1, 0.f) + log1pf(expf(-fabsf(v1)));
                    }
                    *(float2*)(C + (size_t)m * N + n) = make_float2(v0, v1);
                    if (EPI == 2 && n < DTRANK) {      // fused dt hi/lo split
                        __nv_bfloat16 h0 = __float2bfloat16(v0);
                        __nv_bfloat16 h1 = __float2bfloat16(v1);
                        __nv_bfloat16 l0 = __float2bfloat16(v0 - __bfloat162float(h0));
                        __nv_bfloat16 l1 = __float2bfloat16(v1 - __bfloat162float(h1));
                        size_t o = (size_t)m * DTRANK + n;
                        *(__nv_bfloat162*)(dth + o) = __nv_bfloat162(h0, h1);
                        *(__nv_bfloat162*)(dtl + o) = __nv_bfloat162(l0, l1);
                    }
                }
            }
        }
}

// ---------------- fp32 -> (hi, lo) bf16 split, contiguous ----------------
__global__ __launch_bounds__(256) void split_hl(
    const float* __restrict__ src, __nv_bfloat16* __restrict__ h,
    __nv_bfloat16* __restrict__ l, int n4)
{
    int i = blockIdx.x * 256 + threadIdx.x;
    if (i >= n4) return;
    float4 v = ((const float4*)src)[i];
    __nv_bfloat16 h0 = __float2bfloat16(v.x), h1 = __float2bfloat16(v.y);
    __nv_bfloat16 h2 = __float2bfloat16(v.z), h3 = __float2bfloat16(v.w);
    __nv_bfloat16 l0 = __float2bfloat16(v.x - __bfloat162float(h0));
    __nv_bfloat16 l1 = __float2bfloat16(v.y - __bfloat162float(h1));
    __nv_bfloat16 l2 = __float2bfloat16(v.z - __bfloat162float(h2));
    __nv_bfloat16 l3 = __float2bfloat16(v.w - __bfloat162float(h3));
    ((__nv_bfloat162*)h)[i * 2 + 0] = __nv_bfloat162(h0, h1);
    ((__nv_bfloat162*)h)[i * 2 + 1] = __nv_bfloat162(h2, h3);
    ((__nv_bfloat162*)l)[i * 2 + 0] = __nv_bfloat162(l0, l1);
    ((__nv_bfloat162*)l)[i * 2 + 1] = __nv_bfloat162(l2, l3);
}

// ---------------- causal depthwise conv (k=4) + bias + SiLU + bf16 split ----
// Register-reuse version: each thread computes 4 consecutive l outputs for one
// d, loading a 7-row window once (global reads cut ~2.3x). 2 batches from b0.
__global__ __launch_bounds__(256) void conv_silu_kernel(
    const float* __restrict__ w, const float* __restrict__ bias, int b0)
{
    int idx = blockIdx.x * blockDim.x + threadIdx.x;   // over RH*DIN/4
    if (idx >= RH * DIN / 4) return;
    int d  = idx & (DIN - 1);
    int lq = (idx >> 11) & (LEN / 4 - 1);
    int b  = b0 + (idx >> 20);                          // 2048*512 = 2^20 per batch
    int l0 = lq * 4;

    const float* wd = w + d * DCONV;
    float w0 = wd[0], w1 = wd[1], w2 = wd[2], w3 = wd[3];
    float bd = bias[d];

    float xwin[7];
#pragma unroll
    for (int t = 0; t < 7; t++) {
        int ll = l0 - 3 + t;
        xwin[t] = (ll >= 0) ? g_xz[((size_t)(b * LEN + ll)) * (2 * DIN) + d] : 0.f;
    }

#pragma unroll
    for (int k = 0; k < 4; k++) {
        float acc = bd;
        acc = fmaf(w0, xwin[k + 0], acc);
        acc = fmaf(w1, xwin[k + 1], acc);
        acc = fmaf(w2, xwin[k + 2], acc);
        acc = fmaf(w3, xwin[k + 3], acc);
        float s = acc / (1.f + __expf(-acc));
        size_t gidx = ((size_t)(b * LEN + l0 + k)) * DIN + d;
        g_xc[gidx] = s;
        __nv_bfloat16 hi = __float2bfloat16(s);
        g_xch[gidx] = hi;
        g_xcl[gidx] = __float2bfloat16(s - __bfloat162float(hi));
    }
}

// ---------------- selective scan + D skip + SiLU(z) gate + bf16 split ------
// grid (DIN/32, 2), 256 threads: 32 channels x 8 state-pair threads.
// B/C prefetched one iteration ahead (pulls L1 latency off the serial chain).
__global__ __launch_bounds__(256) void scan_kernel(
    const float* __restrict__ A_raw, const float* __restrict__ Dp, int b0)
{
    const int b = b0 + blockIdx.y;
    const int d = blockIdx.x * 32 + (threadIdx.x >> 3);
    const int q = threadIdx.x & 7;
    const int n0 = q * 2;

    float A2[2];
#pragma unroll
    for (int n = 0; n < 2; n++)
        A2[n] = -expf(A_raw[(size_t)(n0 + n) * DIN + d]) * 1.4426950408889634f;
    const float Dd = Dp[d];

    float h0 = 0.f, h1 = 0.f;
    const float* dbcb = g_dbc + (size_t)b * LEN * DBCW + DTRANK;
    const size_t base = (size_t)b * LEN;

    // prefetch l = 0
    size_t r0 = base * DIN + d;
    float dlt = g_delta[r0];
    float xv  = g_xc[r0];
    float zv  = g_xz[base * (2 * DIN) + DIN + d];
    float pB0 = dbcb[n0], pB1 = dbcb[n0 + 1];
    float pC0 = dbcb[DSTATE + n0], pC1 = dbcb[DSTATE + n0 + 1];

    for (int l = 0; l < LEN; l++) {
        float c_dlt = dlt, c_x = xv, c_z = zv;
        float cB0 = pB0, cB1 = pB1, cC0 = pC0, cC1 = pC1;

        int ln = (l + 1 < LEN) ? l + 1 : l;            // prefetch next
        size_t rn = (base + ln) * DIN + d;
        dlt = g_delta[rn];
        xv  = g_xc[rn];
        zv  = g_xz[(base + ln) * (2 * DIN) + DIN + d];
        const float* bcn = dbcb + (size_t)ln * DBCW;
        pB0 = bcn[n0]; pB1 = bcn[n0 + 1];
        pC0 = bcn[DSTATE + n0]; pC1 = bcn[DSTATE + n0 + 1];

        float dx = c_dlt * c_x;
        float dA0 = exp2f(c_dlt * A2[0]);
        float dA1 = exp2f(c_dlt * A2[1]);
        h0 = fmaf(dA0, h0, cB0 * dx);
        h1 = fmaf(dA1, h1, cB1 * dx);
        float yv = fmaf(cC0, h0, cC1 * h1);
        yv += __shfl_xor_sync(0xFFFFFFFFu, yv, 1);
        yv += __shfl_xor_sync(0xFFFFFFFFu, yv, 2);
        yv += __shfl_xor_sync(0xFFFFFFFFu, yv, 4);
        if (q == 0) {
            float y = fmaf(Dd, c_x, yv);
            float gate = c_z / (1.f + __expf(-c_z));
            float o = y * gate;
            size_t oi = (base + l) * DIN + d;
            __nv_bfloat16 hi = __float2bfloat16(o);
            g_yh[oi] = hi;
            g_yl[oi] = __float2bfloat16(o - __bfloat162float(hi));
        }
    }
}

// ---------------- launch: 2 batch-half chains on 2 streams -----------------
extern "C" void kernel_launch(void* const* d_in, const int* in_sizes, int n_in,
                              void* d_out, int out_size)
{
    const float* x      = (const float*)d_in[0];
    const float* W_in   = (const float*)d_in[1];
    const float* conv_w = (const float*)d_in[2];
    const float* conv_b = (const float*)d_in[3];
    const float* W_x    = (const float*)d_in[4];
    const float* W_dt   = (const float*)d_in[5];
    const float* b_dt   = (const float*)d_in[6];
    const float* A_raw  = (const float*)d_in[7];
    const float* Dp     = (const float*)d_in[8];
    const float* W_out  = (const float*)d_in[9];
    float* out = (float*)d_out;

    float *p_xz, *p_dbc, *p_delta;
    __nv_bfloat16 *p_xh, *p_xl, *p_Winh, *p_Winl, *p_xch, *p_xcl, *p_Wxh, *p_Wxl;
    __nv_bfloat16 *p_dth, *p_dtl, *p_Wdth, *p_Wdtl, *p_yh, *p_yl, *p_Wouth, *p_Woutl;
    cudaGetSymbolAddress((void**)&p_xz,    g_xz);
    cudaGetSymbolAddress((void**)&p_dbc,   g_dbc);
    cudaGetSymbolAddress((void**)&p_delta, g_delta);
    cudaGetSymbolAddress((void**)&p_xh,    g_xh);
    cudaGetSymbolAddress((void**)&p_xl,    g_xl);
    cudaGetSymbolAddress((void**)&p_Winh,  g_Winh);
    cudaGetSymbolAddress((void**)&p_Winl,  g_Winl);
    cudaGetSymbolAddress((void**)&p_xch,   g_xch);
    cudaGetSymbolAddress((void**)&p_xcl,   g_xcl);
    cudaGetSymbolAddress((void**)&p_Wxh,   g_Wxh);
    cudaGetSymbolAddress((void**)&p_Wxl,   g_Wxl);
    cudaGetSymbolAddress((void**)&p_dth,   g_dth);
    cudaGetSymbolAddress((void**)&p_dtl,   g_dtl);
    cudaGetSymbolAddress((void**)&p_Wdth,  g_Wdth);
    cudaGetSymbolAddress((void**)&p_Wdtl,  g_Wdtl);
    cudaGetSymbolAddress((void**)&p_yh,    g_yh);
    cudaGetSymbolAddress((void**)&p_yl,    g_yl);
    cudaGetSymbolAddress((void**)&p_Wouth, g_Wouth);
    cudaGetSymbolAddress((void**)&p_Woutl, g_Woutl);

    const int GSMEM = 1024 + 4 * 16384;   // align slack + 2 stages x (A16K+B16K)
    static bool s_init = false;
    static cudaStream_t st0, st1, stw;
    static cudaEvent_t evS, evWin, evWx, evWdt, evWout, evD0, evD1;
    if (!s_init) {
        cudaFuncSetAttribute(gemm_hl<0>, cudaFuncAttributeMaxDynamicSharedMemorySize, GSMEM);
        cudaFuncSetAttribute(gemm_hl<1>, cudaFuncAttributeMaxDynamicSharedMemorySize, GSMEM);
        cudaFuncSetAttribute(gemm_hl<2>, cudaFuncAttributeMaxDynamicSharedMemorySize, GSMEM);
        cudaStreamCreateWithFlags(&st0, cudaStreamNonBlocking);
        cudaStreamCreateWithFlags(&st1, cudaStreamNonBlocking);
        cudaStreamCreateWithFlags(&stw, cudaStreamNonBlocking);
        cudaEventCreateWithFlags(&evS,    cudaEventDisableTiming);
        cudaEventCreateWithFlags(&evWin,  cudaEventDisableTiming);
        cudaEventCreateWithFlags(&evWx,   cudaEventDisableTiming);
        cudaEventCreateWithFlags(&evWdt,  cudaEventDisableTiming);
        cudaEventCreateWithFlags(&evWout, cudaEventDisableTiming);
        cudaEventCreateWithFlags(&evD0,   cudaEventDisableTiming);
        cudaEventCreateWithFlags(&evD1,   cudaEventDisableTiming);
        s_init = true;
    }

    // fork from the origin (capture) stream
    cudaEventRecord(evS, 0);
    cudaStreamWaitEvent(st0, evS, 0);
    cudaStreamWaitEvent(st1, evS, 0);
    cudaStreamWaitEvent(stw, evS, 0);

    // weight splits on stw
    split_hl<<<(2 * DIN * DMODEL / 4 + 255) / 256, 256, 0, stw>>>(
        W_in, p_Winh, p_Winl, 2 * DIN * DMODEL / 4);
    cudaEventRecord(evWin, stw);
    split_hl<<<(DBCW * DIN / 4 + 255) / 256, 256, 0, stw>>>(
        W_x, p_Wxh, p_Wxl, DBCW * DIN / 4);
    cudaEventRecord(evWx, stw);
    split_hl<<<(DIN * DTRANK / 4 + 255) / 256, 256, 0, stw>>>(
        W_dt, p_Wdth, p_Wdtl, DIN * DTRANK / 4);
    cudaEventRecord(evWdt, stw);
    split_hl<<<(DMODEL * DIN / 4 + 255) / 256, 256, 0, stw>>>(
        W_out, p_Wouth, p_Woutl, DMODEL * DIN / 4);
    cudaEventRecord(evWout, stw);

    // two batch-half chains
    for (int h = 0; h < 2; h++) {
        cudaStream_t s = h ? st1 : st0;
        const size_t r0 = (size_t)h * RH;

        // split x half
        split_hl<<<(RH * DMODEL / 4 + 255) / 256, 256, 0, s>>>(
            x + r0 * DMODEL, p_xh + r0 * DMODEL, p_xl + r0 * DMODEL, RH * DMODEL / 4);
        // in-proj GEMM: (4096 x 4096) K=1024
        cudaStreamWaitEvent(s, evWin, 0);
        gemm_hl<0><<<dim3(32, RH / 128), 256, GSMEM, s>>>(
            p_xh + r0 * DMODEL, p_xl + r0 * DMODEL, p_Winh, p_Winl,
            p_xz + r0 * 2 * DIN, 4096, DMODEL, nullptr, nullptr, nullptr);
        // conv + SiLU + xc bf16 split (register-reuse)
        conv_silu_kernel<<<(RH * DIN / 4 + 255) / 256, 256, 0, s>>>(conv_w, conv_b, 2 * h);
        // x-proj GEMM (4096 x 96) K=2048, fused dt split
        cudaStreamWaitEvent(s, evWx, 0);
        gemm_hl<2><<<dim3(1, RH / 128), 256, GSMEM, s>>>(
            p_xch + r0 * DIN, p_xcl + r0 * DIN, p_Wxh, p_Wxl,
            p_dbc + r0 * DBCW, DBCW, DIN, nullptr,
            p_dth + r0 * DTRANK, p_dtl + r0 * DTRANK);
        // delta GEMM (4096 x 2048) K=64, fused bias+softplus
        cudaStreamWaitEvent(s, evWdt, 0);
        gemm_hl<1><<<dim3(16, RH / 128), 256, GSMEM, s>>>(
            p_dth + r0 * DTRANK, p_dtl + r0 * DTRANK, p_Wdth, p_Wdtl,
            p_delta + r0 * DIN, DIN, DTRANK, b_dt, nullptr, nullptr);
        // selective scan (2 batches, 8 threads/channel)
        scan_kernel<<<dim3(DIN / 32, 2), 256, 0, s>>>(A_raw, Dp, 2 * h);
        // out-proj GEMM (4096 x 1024) K=2048
        cudaStreamWaitEvent(s, evWout, 0);
        gemm_hl<0><<<dim3(8, RH / 128), 256, GSMEM, s>>>(
            p_yh + r0 * DIN, p_yl + r0 * DIN, p_Wouth, p_Woutl,
            out + r0 * DMODEL, DMODEL, DIN, nullptr, nullptr, nullptr);
        cudaEventRecord(h ? evD1 : evD0, s);
    }

    // join back onto the origin stream
    cudaStreamWaitEvent(0, evD0, 0);
    cudaStreamWaitEvent(0, evD1, 0);
}